// round 2
// baseline (speedup 1.0000x reference)
#include <cuda_runtime.h>
#include <math.h>

// ---------------- static scratch (no runtime allocation allowed) ----------------
#define MAXN 50000
#define MAXE 400000

__device__ float g_hl[MAXN * 256];
__device__ float g_hr[MAXN * 256];
__device__ float g_h [MAXN * 256];
__device__ float g_hn[MAXN * 256];
__device__ int   g_rowptr[MAXN + 1];
__device__ int   g_csrsrc[MAXE];
__device__ int   g_deg[MAXN];
__device__ int   g_cursor[MAXN];
__device__ float g_bnsum[256];
__device__ float g_bnsq[256];
__device__ float g_scale[256];
__device__ float g_shift[256];

// ---------------- packed f32x2 helpers (Blackwell FFMA2: 2 FLOP/inst) ----------------
__device__ __forceinline__ unsigned long long pack2(float x, float y) {
    unsigned long long r;
    asm("mov.b64 %0, {%1, %2};" : "=l"(r) : "f"(x), "f"(y));
    return r;
}
__device__ __forceinline__ float2 unpack2(unsigned long long v) {
    float2 r;
    asm("mov.b64 {%0, %1}, %2;" : "=f"(r.x), "=f"(r.y) : "l"(v));
    return r;
}
__device__ __forceinline__ unsigned long long ffma2(unsigned long long a,
                                                    unsigned long long b,
                                                    unsigned long long c) {
    unsigned long long d;
    asm("fma.rn.f32x2 %0, %1, %2, %3;" : "=l"(d) : "l"(a), "l"(b), "l"(c));
    return d;
}

// ---------------- GEMM: C[M,256] = A[M,K] @ B[K,256], fp32, f32x2-packed ----------------
// Tile 128x128x16, 256 threads, 8x8 per thread (acc pairs along N).
__global__ __launch_bounds__(256) void gemm_kernel(
    const float* __restrict__ A, const float* __restrict__ B,
    float* __restrict__ C, int M, int K)
{
    __shared__ float As[16][132];   // [k][m], row 528B (16B aligned), padded vs bank conflicts
    __shared__ float Bs[16][128];   // [k][n]

    int t  = threadIdx.x;
    int tx = t & 15, ty = t >> 4;
    int bm = blockIdx.y * 128;
    int bn = blockIdx.x * 128;

    unsigned long long acc[8][4];
#pragma unroll
    for (int i = 0; i < 8; i++)
#pragma unroll
        for (int j = 0; j < 4; j++) acc[i][j] = 0ull;

    for (int k0 = 0; k0 < K; k0 += 16) {
        // load A tile (transposed into As[k][m]), float4 along K
#pragma unroll
        for (int it = 0; it < 2; it++) {
            int lin = t + it * 256;
            int m = lin >> 2, kq = lin & 3;
            float4 v = make_float4(0.f, 0.f, 0.f, 0.f);
            int gr = bm + m;
            if (gr < M) v = *(const float4*)(A + (size_t)gr * K + k0 + kq * 4);
            As[kq * 4 + 0][m] = v.x;
            As[kq * 4 + 1][m] = v.y;
            As[kq * 4 + 2][m] = v.z;
            As[kq * 4 + 3][m] = v.w;
        }
        // load B tile, float4 along N (coalesced)
#pragma unroll
        for (int it = 0; it < 2; it++) {
            int lin = t + it * 256;
            int r = lin >> 5, c4 = lin & 31;
            float4 v = *(const float4*)(B + (size_t)(k0 + r) * 256 + bn + c4 * 4);
            *(float4*)&Bs[r][c4 * 4] = v;
        }
        __syncthreads();

#pragma unroll
        for (int kk = 0; kk < 16; kk++) {
            float4 a0 = *(const float4*)&As[kk][ty * 8];
            float4 a1 = *(const float4*)&As[kk][ty * 8 + 4];
            float4 b0 = *(const float4*)&Bs[kk][tx * 8];
            float4 b1 = *(const float4*)&Bs[kk][tx * 8 + 4];
            unsigned long long bp0 = pack2(b0.x, b0.y);
            unsigned long long bp1 = pack2(b0.z, b0.w);
            unsigned long long bp2 = pack2(b1.x, b1.y);
            unsigned long long bp3 = pack2(b1.z, b1.w);
            float av[8] = {a0.x, a0.y, a0.z, a0.w, a1.x, a1.y, a1.z, a1.w};
#pragma unroll
            for (int i = 0; i < 8; i++) {
                unsigned long long ap = pack2(av[i], av[i]);
                acc[i][0] = ffma2(ap, bp0, acc[i][0]);
                acc[i][1] = ffma2(ap, bp1, acc[i][1]);
                acc[i][2] = ffma2(ap, bp2, acc[i][2]);
                acc[i][3] = ffma2(ap, bp3, acc[i][3]);
            }
        }
        __syncthreads();
    }

#pragma unroll
    for (int i = 0; i < 8; i++) {
        int gr = bm + ty * 8 + i;
        if (gr >= M) continue;
        float2 v0 = unpack2(acc[i][0]), v1 = unpack2(acc[i][1]);
        float2 v2 = unpack2(acc[i][2]), v3 = unpack2(acc[i][3]);
        float* cp = C + (size_t)gr * 256 + bn + tx * 8;
        *(float4*)cp       = make_float4(v0.x, v0.y, v1.x, v1.y);
        *(float4*)(cp + 4) = make_float4(v2.x, v2.y, v3.x, v3.y);
    }
}

// ---------------- CSR build ----------------
__global__ void hist_kernel(const int* __restrict__ dst, int* __restrict__ deg, int E) {
    int e = blockIdx.x * 256 + threadIdx.x;
    if (e < E) atomicAdd(&deg[dst[e]], 1);
}

__global__ void scan_kernel(const int* __restrict__ deg, int* __restrict__ rowptr, int N) {
    __shared__ int sh[1024];
    __shared__ int carry_s;
    int t = threadIdx.x;
    if (t == 0) carry_s = 0;
    __syncthreads();
    for (int base = 0; base < N; base += 1024) {
        int i = base + t;
        int v = (i < N) ? deg[i] : 0;
        sh[t] = v;
        __syncthreads();
        for (int off = 1; off < 1024; off <<= 1) {
            int u = (t >= off) ? sh[t - off] : 0;
            __syncthreads();
            sh[t] += u;
            __syncthreads();
        }
        int carry = carry_s;
        if (i < N) rowptr[i] = carry + sh[t] - v;
        __syncthreads();
        if (t == 1023) carry_s = carry + sh[1023];
        __syncthreads();
    }
    if (t == 0) rowptr[N] = carry_s;
}

__global__ void scatter_kernel(const int* __restrict__ src, const int* __restrict__ dst,
                               const int* __restrict__ rowptr, int* __restrict__ cursor,
                               int* __restrict__ csrsrc, int E) {
    int e = blockIdx.x * 256 + threadIdx.x;
    if (e < E) {
        int d = dst[e];
        int pos = atomicAdd(&cursor[d], 1);
        csrsrc[rowptr[d] + pos] = src[e];
    }
}

// ---------------- GATv2 aggregate: one warp per dst node, online softmax ----------------
// lane l owns dims [8l, 8l+8) -> head = l>>3 (all of a lane's dims in one head).
__global__ __launch_bounds__(256) void gat_kernel(
    const float* __restrict__ hl, const float* __restrict__ hr,
    const int* __restrict__ rowptr, const int* __restrict__ csrsrc,
    const float* __restrict__ att, const float* __restrict__ bias,
    float* __restrict__ out, int N)
{
    int warp = (blockIdx.x * blockDim.x + threadIdx.x) >> 5;
    if (warp >= N) return;
    int lane = threadIdx.x & 31;
    int d = warp;
    int base = lane * 8;

    float4 at0 = *(const float4*)(att + base);
    float4 at1 = *(const float4*)(att + base + 4);
    float atv[8] = {at0.x, at0.y, at0.z, at0.w, at1.x, at1.y, at1.z, at1.w};

    const float* hrp = hr + (size_t)d * 256 + base;
    float4 r0 = *(const float4*)hrp;
    float4 r1 = *(const float4*)(hrp + 4);
    float hrv[8] = {r0.x, r0.y, r0.z, r0.w, r1.x, r1.y, r1.z, r1.w};

    float m = -1.0e30f, den = 0.f;
    float acc[8] = {0.f, 0.f, 0.f, 0.f, 0.f, 0.f, 0.f, 0.f};

    int e0 = rowptr[d], e1 = rowptr[d + 1];
    for (int e = e0 - 1; e < e1; e++) {          // e == e0-1 -> self loop
        int s = (e < e0) ? d : csrsrc[e];
        const float* hp = hl + (size_t)s * 256 + base;
        float4 h0 = *(const float4*)hp;
        float4 h1 = *(const float4*)(hp + 4);
        float hv[8] = {h0.x, h0.y, h0.z, h0.w, h1.x, h1.y, h1.z, h1.w};

        float p = 0.f;
#pragma unroll
        for (int j = 0; j < 8; j++) {
            float v = hv[j] + hrv[j];
            v = (v > 0.f) ? v : 0.2f * v;        // attention leaky-relu slope 0.2
            p += v * atv[j];
        }
        // reduce within 8-lane head group
        p += __shfl_xor_sync(0xffffffffu, p, 1);
        p += __shfl_xor_sync(0xffffffffu, p, 2);
        p += __shfl_xor_sync(0xffffffffu, p, 4);

        float nm = fmaxf(m, p);
        float f  = __expf(m - nm);
        float w  = __expf(p - nm);
        den = den * f + w;
        m = nm;
#pragma unroll
        for (int j = 0; j < 8; j++) acc[j] = acc[j] * f + w * hv[j];
    }

    float inv = 1.f / (den + 1e-16f);
    float* op = out + (size_t)d * 256 + base;
    float4 o0, o1;
    o0.x = acc[0] * inv + bias[base + 0];
    o0.y = acc[1] * inv + bias[base + 1];
    o0.z = acc[2] * inv + bias[base + 2];
    o0.w = acc[3] * inv + bias[base + 3];
    o1.x = acc[4] * inv + bias[base + 4];
    o1.y = acc[5] * inv + bias[base + 5];
    o1.z = acc[6] * inv + bias[base + 6];
    o1.w = acc[7] * inv + bias[base + 7];
    *(float4*)op       = o0;
    *(float4*)(op + 4) = o1;
}

// ---------------- BatchNorm ----------------
__global__ void bn_stats_kernel(const float* __restrict__ x,
                                float* __restrict__ bnsum, float* __restrict__ bnsq, int N) {
    int c = threadIdx.x;                          // 256 threads, thread = feature
    float s = 0.f, q = 0.f;
    for (int r = blockIdx.x; r < N; r += gridDim.x) {
        float v = x[(size_t)r * 256 + c];
        s += v;
        q += v * v;
    }
    atomicAdd(&bnsum[c], s);
    atomicAdd(&bnsq[c], q);
}

__global__ void bn_final_kernel(const float* __restrict__ bnsum, const float* __restrict__ bnsq,
                                const float* __restrict__ g, const float* __restrict__ b,
                                float* __restrict__ scale, float* __restrict__ shift, int N) {
    int c = threadIdx.x;
    float invn = 1.f / (float)N;
    float mean = bnsum[c] * invn;
    float var  = bnsq[c] * invn - mean * mean;
    float sc   = g[c] * rsqrtf(var + 1e-5f);
    scale[c] = sc;
    shift[c] = b[c] - mean * sc;
}

__global__ void bn_apply_kernel(const float* __restrict__ in, float* __restrict__ outp,
                                const float* __restrict__ scale, const float* __restrict__ shift,
                                int N) {
    int i = blockIdx.x * 256 + threadIdx.x;       // one float4 per thread
    if (i >= N * 64) return;
    int c = (i & 63) * 4;
    float4 v  = *(const float4*)(in + (size_t)i * 4);
    float4 sc = *(const float4*)(scale + c);
    float4 sh = *(const float4*)(shift + c);
    float a0 = v.x * sc.x + sh.x;
    float a1 = v.y * sc.y + sh.y;
    float a2 = v.z * sc.z + sh.z;
    float a3 = v.w * sc.w + sh.w;
    float4 o;
    o.x = (a0 > 0.f) ? a0 : 0.01f * a0;
    o.y = (a1 > 0.f) ? a1 : 0.01f * a1;
    o.z = (a2 > 0.f) ? a2 : 0.01f * a2;
    o.w = (a3 > 0.f) ? a3 : 0.01f * a3;
    *(float4*)(outp + (size_t)i * 4) = o;
}

// ---------------- Classifier: warp per row, 2 outputs ----------------
__global__ __launch_bounds__(256) void classifier_kernel(
    const float* __restrict__ h, const float* __restrict__ cW,
    const float* __restrict__ cb, float* __restrict__ outp, int N)
{
    int warp = (blockIdx.x * blockDim.x + threadIdx.x) >> 5;
    if (warp >= N) return;
    int lane = threadIdx.x & 31;

    const float* hp = h + (size_t)warp * 256 + lane * 8;
    float4 h0 = *(const float4*)hp;
    float4 h1 = *(const float4*)(hp + 4);
    float hv[8] = {h0.x, h0.y, h0.z, h0.w, h1.x, h1.y, h1.z, h1.w};

    const float* wp = cW + lane * 16;             // cW is [256,2] row-major
    float4 w0 = *(const float4*)(wp + 0);
    float4 w1 = *(const float4*)(wp + 4);
    float4 w2 = *(const float4*)(wp + 8);
    float4 w3 = *(const float4*)(wp + 12);
    float wv[16] = {w0.x, w0.y, w0.z, w0.w, w1.x, w1.y, w1.z, w1.w,
                    w2.x, w2.y, w2.z, w2.w, w3.x, w3.y, w3.z, w3.w};

    float c0 = 0.f, c1 = 0.f;
#pragma unroll
    for (int j = 0; j < 8; j++) {
        c0 += hv[j] * wv[2 * j];
        c1 += hv[j] * wv[2 * j + 1];
    }
#pragma unroll
    for (int off = 16; off > 0; off >>= 1) {
        c0 += __shfl_xor_sync(0xffffffffu, c0, off);
        c1 += __shfl_xor_sync(0xffffffffu, c1, off);
    }
    if (lane == 0) {
        outp[(size_t)warp * 2 + 0] = c0 + cb[0];
        outp[(size_t)warp * 2 + 1] = c1 + cb[1];
    }
}

// ---------------- launch ----------------
extern "C" void kernel_launch(void* const* d_in, const int* in_sizes, int n_in,
                              void* d_out, int out_size) {
    const float* x[3];
    const int*   ei[3];
    for (int i = 0; i < 3; i++) {
        x[i]  = (const float*)d_in[i];
        ei[i] = (const int*)d_in[3 + i];
    }
    const float* Wl1  = (const float*)d_in[6];
    const float* Wr1  = (const float*)d_in[7];
    const float* att1 = (const float*)d_in[8];
    const float* b1   = (const float*)d_in[9];
    const float* Wl2  = (const float*)d_in[10];
    const float* Wr2  = (const float*)d_in[11];
    const float* att2 = (const float*)d_in[12];
    const float* b2   = (const float*)d_in[13];
    const float* bng  = (const float*)d_in[14];
    const float* bnb  = (const float*)d_in[15];
    const float* cW   = (const float*)d_in[16];
    const float* cb   = (const float*)d_in[17];
    float* out = (float*)d_out;

    float *hl, *hr, *h, *hn, *bnsum, *bnsq, *scale, *shift;
    int *rowptr, *csrsrc, *deg, *cursor;
    cudaGetSymbolAddress((void**)&hl,     g_hl);
    cudaGetSymbolAddress((void**)&hr,     g_hr);
    cudaGetSymbolAddress((void**)&h,      g_h);
    cudaGetSymbolAddress((void**)&hn,     g_hn);
    cudaGetSymbolAddress((void**)&rowptr, g_rowptr);
    cudaGetSymbolAddress((void**)&csrsrc, g_csrsrc);
    cudaGetSymbolAddress((void**)&deg,    g_deg);
    cudaGetSymbolAddress((void**)&cursor, g_cursor);
    cudaGetSymbolAddress((void**)&bnsum,  g_bnsum);
    cudaGetSymbolAddress((void**)&bnsq,   g_bnsq);
    cudaGetSymbolAddress((void**)&scale,  g_scale);
    cudaGetSymbolAddress((void**)&shift,  g_shift);

    int row_off = 0;
    for (int i = 0; i < 3; i++) {
        int N = in_sizes[i] / 128;
        int E = in_sizes[3 + i] / 2;
        const int* src = ei[i];
        const int* dst = ei[i] + E;

        // CSR build (shared by both GAT layers)
        cudaMemsetAsync(deg, 0, N * sizeof(int), 0);
        hist_kernel<<<(E + 255) / 256, 256>>>(dst, deg, E);
        scan_kernel<<<1, 1024>>>(deg, rowptr, N);
        cudaMemsetAsync(cursor, 0, N * sizeof(int), 0);
        scatter_kernel<<<(E + 255) / 256, 256>>>(src, dst, rowptr, cursor, csrsrc, E);

        const float* in = x[i];
        int K = 128;
        const float* wl = Wl1 + (size_t)i * 128 * 256;
        const float* wr = Wr1 + (size_t)i * 128 * 256;
        const float* at = att1 + i * 256;
        const float* bs = b1 + i * 256;

        for (int layer = 0; layer < 2; layer++) {
            dim3 g(2, (N + 127) / 128);
            gemm_kernel<<<g, 256>>>(in, wl, hl, N, K);
            gemm_kernel<<<g, 256>>>(in, wr, hr, N, K);
            gat_kernel<<<(N * 32 + 255) / 256, 256>>>(hl, hr, rowptr, csrsrc, at, bs, h, N);

            cudaMemsetAsync(bnsum, 0, 256 * sizeof(float), 0);
            cudaMemsetAsync(bnsq,  0, 256 * sizeof(float), 0);
            bn_stats_kernel<<<240, 256>>>(h, bnsum, bnsq, N);
            bn_final_kernel<<<1, 256>>>(bnsum, bnsq, bng + i * 256, bnb + i * 256,
                                        scale, shift, N);
            bn_apply_kernel<<<(N * 64 + 255) / 256, 256>>>(h, hn, scale, shift, N);

            // switch to layer-2 parameters
            in = hn;
            K = 256;
            wl = Wl2 + (size_t)i * 256 * 256;
            wr = Wr2 + (size_t)i * 256 * 256;
            at = att2 + i * 256;
            bs = b2 + i * 256;
        }

        classifier_kernel<<<(N * 32 + 255) / 256, 256>>>(hn, cW, cb,
                                                         out + (size_t)row_off * 2, N);
        row_off += N;
    }
}

// round 8
// speedup vs baseline: 1.4491x; 1.4491x over previous
#include <cuda_runtime.h>
#include <cuda_bf16.h>
#include <math.h>
#include <stdint.h>

// ---------------- static scratch (no runtime allocation allowed) ----------------
#define MAXN 50000
#define MAXE 400000

__device__ float g_hl[MAXN * 256];
__device__ float g_hr[MAXN * 256];
__device__ float g_h [MAXN * 256];
__device__ float g_hn[MAXN * 256];
__device__ __nv_bfloat16 g_Ah[MAXN * 256];
__device__ __nv_bfloat16 g_Al[MAXN * 256];
__device__ __nv_bfloat16 g_BLh[256 * 256];
__device__ __nv_bfloat16 g_BLl[256 * 256];
__device__ __nv_bfloat16 g_BRh[256 * 256];
__device__ __nv_bfloat16 g_BRl[256 * 256];
__device__ int   g_rowptr[MAXN + 1];
__device__ int   g_csrsrc[MAXE];
__device__ int   g_deg[MAXN];
__device__ int   g_cursor[MAXN];
__device__ float g_bnsum[256];
__device__ float g_bnsq[256];
__device__ float g_scale[256];
__device__ float g_shift[256];

// ---------------- baseline-PTX helpers (no 'a'-suffix features) ----------------
__device__ __forceinline__ uint32_t smem_u32(const void* p) {
    uint32_t a;
    asm("{ .reg .u64 t; cvta.to.shared.u64 t, %1; cvt.u32.u64 %0, t; }" : "=r"(a) : "l"(p));
    return a;
}
__device__ __forceinline__ void cp_async16(uint32_t dst, const void* src) {
    asm volatile("cp.async.cg.shared.global [%0], [%1], 16;" :: "r"(dst), "l"(src));
}
__device__ __forceinline__ void cp_async16_pred(uint32_t dst, const void* src, bool pred) {
    int sz = pred ? 16 : 0;
    asm volatile("cp.async.cg.shared.global [%0], [%1], 16, %2;" :: "r"(dst), "l"(src), "r"(sz));
}
__device__ __forceinline__ void cp_commit() { asm volatile("cp.async.commit_group;" ::: "memory"); }
template <int N>
__device__ __forceinline__ void cp_wait() { asm volatile("cp.async.wait_group %0;" :: "n"(N) : "memory"); }

__device__ __forceinline__ void ldmat_x4(uint32_t addr, uint32_t& r0, uint32_t& r1,
                                         uint32_t& r2, uint32_t& r3) {
    asm volatile("ldmatrix.sync.aligned.m8n8.x4.shared.b16 {%0,%1,%2,%3}, [%4];"
                 : "=r"(r0), "=r"(r1), "=r"(r2), "=r"(r3) : "r"(addr));
}
__device__ __forceinline__ void ldmat_x4_t(uint32_t addr, uint32_t& r0, uint32_t& r1,
                                           uint32_t& r2, uint32_t& r3) {
    asm volatile("ldmatrix.sync.aligned.m8n8.x4.trans.shared.b16 {%0,%1,%2,%3}, [%4];"
                 : "=r"(r0), "=r"(r1), "=r"(r2), "=r"(r3) : "r"(addr));
}
__device__ __forceinline__ void mma_bf16(float& c0, float& c1, float& c2, float& c3,
                                         uint32_t a0, uint32_t a1, uint32_t a2, uint32_t a3,
                                         uint32_t b0, uint32_t b1) {
    asm volatile("mma.sync.aligned.m16n8k16.row.col.f32.bf16.bf16.f32 "
                 "{%0,%1,%2,%3}, {%4,%5,%6,%7}, {%8,%9}, {%0,%1,%2,%3};"
                 : "+f"(c0), "+f"(c1), "+f"(c2), "+f"(c3)
                 : "r"(a0), "r"(a1), "r"(a2), "r"(a3), "r"(b0), "r"(b1));
}

// ---------------- HMMA GEMM: C[M,256] = A[M,K] @ B[K,256], bf16 hi/lo split ----------------
// SMEM layout per stage (bytes): Ah[128][40]b16 @0, Al @10240, Bh[32][136]b16 @20480, Bl @29184
#define KC 32
#define A_STR 40
#define B_STR 136
#define S_AH 0
#define S_AL 10240
#define S_BH 20480
#define S_BL 29184
#define STAGE_B 37888
#define GEMM_SMEM (2 * STAGE_B)

__global__ __launch_bounds__(256) void gemm_mma_kernel(
    const __nv_bfloat16* __restrict__ Ah, const __nv_bfloat16* __restrict__ Al,
    const __nv_bfloat16* __restrict__ Bh, const __nv_bfloat16* __restrict__ Bl,
    float* __restrict__ C, int M, int K)
{
    extern __shared__ char smem[];
    const uint32_t sb = smem_u32(smem);
    const int tid  = threadIdx.x;
    const int lane = tid & 31;
    const int w    = tid >> 5;
    const int wm   = (w & 3) * 32;    // warp row block within 128
    const int wn   = (w >> 2) * 64;   // warp col block within 128
    const int bm   = blockIdx.y * 128;
    const int bn   = blockIdx.x * 128;

    float acc[2][8][4];
#pragma unroll
    for (int i = 0; i < 2; i++)
#pragma unroll
        for (int j = 0; j < 8; j++)
#pragma unroll
            for (int k = 0; k < 4; k++) acc[i][j][k] = 0.f;

    const int nc = K >> 5;

    // ---- chunk loader (cp.async) ----
    auto load_chunk = [&](int c) {
        const uint32_t st = sb + (c & 1) * STAGE_B;
        const int k0 = c * KC;
        // A hi/lo: 128 x 32 bf16 = 512 x uint4 per array
#pragma unroll
        for (int it = 0; it < 2; it++) {
            int lin = tid + it * 256;
            int row = lin >> 2, seg = lin & 3;
            bool p = (bm + row) < M;
            const char* gA = (const char*)(Ah + (size_t)(bm + row) * K + k0 + seg * 8);
            const char* gL = (const char*)(Al + (size_t)(bm + row) * K + k0 + seg * 8);
            uint32_t dA = st + S_AH + row * (A_STR * 2) + seg * 16;
            uint32_t dL = st + S_AL + row * (A_STR * 2) + seg * 16;
            cp_async16_pred(dA, gA, p);
            cp_async16_pred(dL, gL, p);
        }
        // B hi/lo: 32 x 128 bf16 = 512 x uint4 per array
#pragma unroll
        for (int it = 0; it < 2; it++) {
            int lin = tid + it * 256;
            int row = lin >> 4, seg = lin & 15;
            const char* gH = (const char*)(Bh + (size_t)(k0 + row) * 256 + bn + seg * 8);
            const char* gL = (const char*)(Bl + (size_t)(k0 + row) * 256 + bn + seg * 8);
            uint32_t dH = st + S_BH + row * (B_STR * 2) + seg * 16;
            uint32_t dL = st + S_BL + row * (B_STR * 2) + seg * 16;
            cp_async16(dH, gH);
            cp_async16(dL, gL);
        }
    };

    load_chunk(0);
    cp_commit();

    for (int c = 0; c < nc; c++) {
        if (c + 1 < nc) { load_chunk(c + 1); cp_commit(); cp_wait<1>(); }
        else            { cp_wait<0>(); }
        __syncthreads();

        const uint32_t st = sb + (c & 1) * STAGE_B;
#pragma unroll
        for (int ks = 0; ks < 2; ks++) {
            const int kk = ks * 16;
            // a-frags: 2 m-tiles, hi+lo
            uint32_t ah[2][4], al[2][4];
#pragma unroll
            for (int mt = 0; mt < 2; mt++) {
                uint32_t off = ((wm + mt * 16 + (lane & 15)) * A_STR + kk + (lane >> 4) * 8) * 2;
                ldmat_x4(st + S_AH + off, ah[mt][0], ah[mt][1], ah[mt][2], ah[mt][3]);
                ldmat_x4(st + S_AL + off, al[mt][0], al[mt][1], al[mt][2], al[mt][3]);
            }
            // b-frags: 4 n-pairs (16 cols each), hi+lo; x4.trans -> 2 n8k16 frags
            uint32_t bh[4][4], bl[4][4];
#pragma unroll
            for (int np = 0; np < 4; np++) {
                uint32_t off = ((kk + (lane & 15)) * B_STR + wn + np * 16 + (lane >> 4) * 8) * 2;
                ldmat_x4_t(st + S_BH + off, bh[np][0], bh[np][1], bh[np][2], bh[np][3]);
                ldmat_x4_t(st + S_BL + off, bl[np][0], bl[np][1], bl[np][2], bl[np][3]);
            }
#pragma unroll
            for (int mt = 0; mt < 2; mt++)
#pragma unroll
                for (int np = 0; np < 4; np++)
#pragma unroll
                    for (int half = 0; half < 2; half++) {
                        int nt = np * 2 + half;
                        float* a = acc[mt][nt];
                        uint32_t b0h = bh[np][half * 2], b1h = bh[np][half * 2 + 1];
                        uint32_t b0l = bl[np][half * 2], b1l = bl[np][half * 2 + 1];
                        mma_bf16(a[0], a[1], a[2], a[3],
                                 ah[mt][0], ah[mt][1], ah[mt][2], ah[mt][3], b0h, b1h);
                        mma_bf16(a[0], a[1], a[2], a[3],
                                 ah[mt][0], ah[mt][1], ah[mt][2], ah[mt][3], b0l, b1l);
                        mma_bf16(a[0], a[1], a[2], a[3],
                                 al[mt][0], al[mt][1], al[mt][2], al[mt][3], b0h, b1h);
                    }
        }
        __syncthreads();
    }

    // epilogue
    const int g4 = lane >> 2, t4 = lane & 3;
#pragma unroll
    for (int mt = 0; mt < 2; mt++) {
        int r0 = bm + wm + mt * 16 + g4;
        int r1 = r0 + 8;
#pragma unroll
        for (int nt = 0; nt < 8; nt++) {
            int col = bn + wn + nt * 8 + t4 * 2;
            if (r0 < M) *(float2*)(C + (size_t)r0 * 256 + col) =
                make_float2(acc[mt][nt][0], acc[mt][nt][1]);
            if (r1 < M) *(float2*)(C + (size_t)r1 * 256 + col) =
                make_float2(acc[mt][nt][2], acc[mt][nt][3]);
        }
    }
}

// ---------------- fp32 -> bf16 hi/lo split (also used for [K,256] weights) ----------------
__global__ void split_kernel(const float* __restrict__ in, __nv_bfloat16* __restrict__ hi,
                             __nv_bfloat16* __restrict__ lo, int n4) {
    int i = blockIdx.x * 256 + threadIdx.x;
    if (i >= n4) return;
    float4 v = ((const float4*)in)[i];
    __nv_bfloat16 h0 = __float2bfloat16(v.x), h1 = __float2bfloat16(v.y);
    __nv_bfloat16 h2 = __float2bfloat16(v.z), h3 = __float2bfloat16(v.w);
    __nv_bfloat16 l0 = __float2bfloat16(v.x - __bfloat162float(h0));
    __nv_bfloat16 l1 = __float2bfloat16(v.y - __bfloat162float(h1));
    __nv_bfloat16 l2 = __float2bfloat16(v.z - __bfloat162float(h2));
    __nv_bfloat16 l3 = __float2bfloat16(v.w - __bfloat162float(h3));
    ((__nv_bfloat162*)hi)[2 * i]     = __halves2bfloat162(h0, h1);
    ((__nv_bfloat162*)hi)[2 * i + 1] = __halves2bfloat162(h2, h3);
    ((__nv_bfloat162*)lo)[2 * i]     = __halves2bfloat162(l0, l1);
    ((__nv_bfloat162*)lo)[2 * i + 1] = __halves2bfloat162(l2, l3);
}

// ---------------- CSR build ----------------
__global__ void hist_kernel(const int* __restrict__ dst, int* __restrict__ deg, int E) {
    int e = blockIdx.x * 256 + threadIdx.x;
    if (e < E) atomicAdd(&deg[dst[e]], 1);
}

__global__ void scan_kernel(const int* __restrict__ deg, int* __restrict__ rowptr, int N) {
    __shared__ int sh[1024];
    __shared__ int carry_s;
    int t = threadIdx.x;
    if (t == 0) carry_s = 0;
    __syncthreads();
    for (int base = 0; base < N; base += 1024) {
        int i = base + t;
        int v = (i < N) ? deg[i] : 0;
        sh[t] = v;
        __syncthreads();
        for (int off = 1; off < 1024; off <<= 1) {
            int u = (t >= off) ? sh[t - off] : 0;
            __syncthreads();
            sh[t] += u;
            __syncthreads();
        }
        int carry = carry_s;
        if (i < N) rowptr[i] = carry + sh[t] - v;
        __syncthreads();
        if (t == 1023) carry_s = carry + sh[1023];
        __syncthreads();
    }
    if (t == 0) rowptr[N] = carry_s;
}

__global__ void scatter_kernel(const int* __restrict__ src, const int* __restrict__ dst,
                               const int* __restrict__ rowptr, int* __restrict__ cursor,
                               int* __restrict__ csrsrc, int E) {
    int e = blockIdx.x * 256 + threadIdx.x;
    if (e < E) {
        int d = dst[e];
        int pos = atomicAdd(&cursor[d], 1);
        csrsrc[rowptr[d] + pos] = src[e];
    }
}

// ---------------- GATv2 aggregate: one warp per dst node, online softmax ----------------
__global__ __launch_bounds__(256) void gat_kernel(
    const float* __restrict__ hl, const float* __restrict__ hr,
    const int* __restrict__ rowptr, const int* __restrict__ csrsrc,
    const float* __restrict__ att, const float* __restrict__ bias,
    float* __restrict__ out, int N)
{
    int warp = (blockIdx.x * blockDim.x + threadIdx.x) >> 5;
    if (warp >= N) return;
    int lane = threadIdx.x & 31;
    int d = warp;
    int base = lane * 8;

    float4 at0 = *(const float4*)(att + base);
    float4 at1 = *(const float4*)(att + base + 4);
    float atv[8] = {at0.x, at0.y, at0.z, at0.w, at1.x, at1.y, at1.z, at1.w};

    const float* hrp = hr + (size_t)d * 256 + base;
    float4 r0 = *(const float4*)hrp;
    float4 r1 = *(const float4*)(hrp + 4);
    float hrv[8] = {r0.x, r0.y, r0.z, r0.w, r1.x, r1.y, r1.z, r1.w};

    float m = -1.0e30f, den = 0.f;
    float acc[8] = {0.f, 0.f, 0.f, 0.f, 0.f, 0.f, 0.f, 0.f};

    int e0 = rowptr[d], e1 = rowptr[d + 1];
    for (int e = e0 - 1; e < e1; e++) {          // e == e0-1 -> self loop
        int s = (e < e0) ? d : csrsrc[e];
        const float* hp = hl + (size_t)s * 256 + base;
        float4 h0 = *(const float4*)hp;
        float4 h1 = *(const float4*)(hp + 4);
        float hv[8] = {h0.x, h0.y, h0.z, h0.w, h1.x, h1.y, h1.z, h1.w};

        float p = 0.f;
#pragma unroll
        for (int j = 0; j < 8; j++) {
            float v = hv[j] + hrv[j];
            v = (v > 0.f) ? v : 0.2f * v;
            p += v * atv[j];
        }
        p += __shfl_xor_sync(0xffffffffu, p, 1);
        p += __shfl_xor_sync(0xffffffffu, p, 2);
        p += __shfl_xor_sync(0xffffffffu, p, 4);

        float nm = fmaxf(m, p);
        float f  = __expf(m - nm);
        float wv = __expf(p - nm);
        den = den * f + wv;
        m = nm;
#pragma unroll
        for (int j = 0; j < 8; j++) acc[j] = acc[j] * f + wv * hv[j];
    }

    float inv = 1.f / (den + 1e-16f);
    float* op = out + (size_t)d * 256 + base;
    float4 o0, o1;
    o0.x = acc[0] * inv + bias[base + 0];
    o0.y = acc[1] * inv + bias[base + 1];
    o0.z = acc[2] * inv + bias[base + 2];
    o0.w = acc[3] * inv + bias[base + 3];
    o1.x = acc[4] * inv + bias[base + 4];
    o1.y = acc[5] * inv + bias[base + 5];
    o1.z = acc[6] * inv + bias[base + 6];
    o1.w = acc[7] * inv + bias[base + 7];
    *(float4*)op       = o0;
    *(float4*)(op + 4) = o1;
}

// ---------------- BatchNorm ----------------
__global__ void bn_stats_kernel(const float* __restrict__ x,
                                float* __restrict__ bnsum, float* __restrict__ bnsq, int N) {
    int c = threadIdx.x;
    float s = 0.f, q = 0.f;
    for (int r = blockIdx.x; r < N; r += gridDim.x) {
        float v = x[(size_t)r * 256 + c];
        s += v;
        q += v * v;
    }
    atomicAdd(&bnsum[c], s);
    atomicAdd(&bnsq[c], q);
}

__global__ void bn_final_kernel(const float* __restrict__ bnsum, const float* __restrict__ bnsq,
                                const float* __restrict__ g, const float* __restrict__ b,
                                float* __restrict__ scale, float* __restrict__ shift, int N) {
    int c = threadIdx.x;
    float invn = 1.f / (float)N;
    float mean = bnsum[c] * invn;
    float var  = bnsq[c] * invn - mean * mean;
    float sc   = g[c] * rsqrtf(var + 1e-5f);
    scale[c] = sc;
    shift[c] = b[c] - mean * sc;
}

__global__ void bn_apply_kernel(const float* __restrict__ in, float* __restrict__ outp,
                                const float* __restrict__ scale, const float* __restrict__ shift,
                                int N) {
    int i = blockIdx.x * 256 + threadIdx.x;
    if (i >= N * 64) return;
    int c = (i & 63) * 4;
    float4 v  = *(const float4*)(in + (size_t)i * 4);
    float4 sc = *(const float4*)(scale + c);
    float4 sh = *(const float4*)(shift + c);
    float a0 = v.x * sc.x + sh.x;
    float a1 = v.y * sc.y + sh.y;
    float a2 = v.z * sc.z + sh.z;
    float a3 = v.w * sc.w + sh.w;
    float4 o;
    o.x = (a0 > 0.f) ? a0 : 0.01f * a0;
    o.y = (a1 > 0.f) ? a1 : 0.01f * a1;
    o.z = (a2 > 0.f) ? a2 : 0.01f * a2;
    o.w = (a3 > 0.f) ? a3 : 0.01f * a3;
    *(float4*)(outp + (size_t)i * 4) = o;
}

// ---------------- Classifier ----------------
__global__ __launch_bounds__(256) void classifier_kernel(
    const float* __restrict__ h, const float* __restrict__ cW,
    const float* __restrict__ cb, float* __restrict__ outp, int N)
{
    int warp = (blockIdx.x * blockDim.x + threadIdx.x) >> 5;
    if (warp >= N) return;
    int lane = threadIdx.x & 31;

    const float* hp = h + (size_t)warp * 256 + lane * 8;
    float4 h0 = *(const float4*)hp;
    float4 h1 = *(const float4*)(hp + 4);
    float hv[8] = {h0.x, h0.y, h0.z, h0.w, h1.x, h1.y, h1.z, h1.w};

    const float* wp = cW + lane * 16;
    float4 w0 = *(const float4*)(wp + 0);
    float4 w1 = *(const float4*)(wp + 4);
    float4 w2 = *(const float4*)(wp + 8);
    float4 w3 = *(const float4*)(wp + 12);
    float wv[16] = {w0.x, w0.y, w0.z, w0.w, w1.x, w1.y, w1.z, w1.w,
                    w2.x, w2.y, w2.z, w2.w, w3.x, w3.y, w3.z, w3.w};

    float c0 = 0.f, c1 = 0.f;
#pragma unroll
    for (int j = 0; j < 8; j++) {
        c0 += hv[j] * wv[2 * j];
        c1 += hv[j] * wv[2 * j + 1];
    }
#pragma unroll
    for (int off = 16; off > 0; off >>= 1) {
        c0 += __shfl_xor_sync(0xffffffffu, c0, off);
        c1 += __shfl_xor_sync(0xffffffffu, c1, off);
    }
    if (lane == 0) {
        outp[(size_t)warp * 2 + 0] = c0 + cb[0];
        outp[(size_t)warp * 2 + 1] = c1 + cb[1];
    }
}

// ---------------- launch ----------------
extern "C" void kernel_launch(void* const* d_in, const int* in_sizes, int n_in,
                              void* d_out, int out_size) {
    const float* x[3];
    const int*   ei[3];
    for (int i = 0; i < 3; i++) {
        x[i]  = (const float*)d_in[i];
        ei[i] = (const int*)d_in[3 + i];
    }
    const float* Wl1  = (const float*)d_in[6];
    const float* Wr1  = (const float*)d_in[7];
    const float* att1 = (const float*)d_in[8];
    const float* b1   = (const float*)d_in[9];
    const float* Wl2  = (const float*)d_in[10];
    const float* Wr2  = (const float*)d_in[11];
    const float* att2 = (const float*)d_in[12];
    const float* b2   = (const float*)d_in[13];
    const float* bng  = (const float*)d_in[14];
    const float* bnb  = (const float*)d_in[15];
    const float* cW   = (const float*)d_in[16];
    const float* cb   = (const float*)d_in[17];
    float* out = (float*)d_out;

    float *hl, *hr, *h, *hn, *bnsum, *bnsq, *scale, *shift;
    __nv_bfloat16 *Ah, *Al, *BLh, *BLl, *BRh, *BRl;
    int *rowptr, *csrsrc, *deg, *cursor;
    cudaGetSymbolAddress((void**)&hl,     g_hl);
    cudaGetSymbolAddress((void**)&hr,     g_hr);
    cudaGetSymbolAddress((void**)&h,      g_h);
    cudaGetSymbolAddress((void**)&hn,     g_hn);
    cudaGetSymbolAddress((void**)&Ah,     g_Ah);
    cudaGetSymbolAddress((void**)&Al,     g_Al);
    cudaGetSymbolAddress((void**)&BLh,    g_BLh);
    cudaGetSymbolAddress((void**)&BLl,    g_BLl);
    cudaGetSymbolAddress((void**)&BRh,    g_BRh);
    cudaGetSymbolAddress((void**)&BRl,    g_BRl);
    cudaGetSymbolAddress((void**)&rowptr, g_rowptr);
    cudaGetSymbolAddress((void**)&csrsrc, g_csrsrc);
    cudaGetSymbolAddress((void**)&deg,    g_deg);
    cudaGetSymbolAddress((void**)&cursor, g_cursor);
    cudaGetSymbolAddress((void**)&bnsum,  g_bnsum);
    cudaGetSymbolAddress((void**)&bnsq,   g_bnsq);
    cudaGetSymbolAddress((void**)&scale,  g_scale);
    cudaGetSymbolAddress((void**)&shift,  g_shift);

    static bool attr_set = false;
    if (!attr_set) {
        cudaFuncSetAttribute(gemm_mma_kernel,
                             cudaFuncAttributeMaxDynamicSharedMemorySize, GEMM_SMEM);
        attr_set = true;
    }

    int row_off = 0;
    for (int i = 0; i < 3; i++) {
        int N = in_sizes[i] / 128;
        int E = in_sizes[3 + i] / 2;
        const int* src = ei[i];
        const int* dst = ei[i] + E;

        // CSR build (shared by both GAT layers)
        cudaMemsetAsync(deg, 0, N * sizeof(int), 0);
        hist_kernel<<<(E + 255) / 256, 256>>>(dst, deg, E);
        scan_kernel<<<1, 1024>>>(deg, rowptr, N);
        cudaMemsetAsync(cursor, 0, N * sizeof(int), 0);
        scatter_kernel<<<(E + 255) / 256, 256>>>(src, dst, rowptr, cursor, csrsrc, E);

        const float* in = x[i];
        int K = 128;
        const float* wl = Wl1 + (size_t)i * 128 * 256;
        const float* wr = Wr1 + (size_t)i * 128 * 256;
        const float* at = att1 + i * 256;
        const float* bs = b1 + i * 256;

        for (int layer = 0; layer < 2; layer++) {
            int n4 = N * K / 4;
            split_kernel<<<(n4 + 255) / 256, 256>>>(in, Ah, Al, n4);
            split_kernel<<<(K * 64 + 255) / 256, 256>>>(wl, BLh, BLl, K * 64);
            split_kernel<<<(K * 64 + 255) / 256, 256>>>(wr, BRh, BRl, K * 64);

            dim3 gg(2, (N + 127) / 128);
            gemm_mma_kernel<<<gg, 256, GEMM_SMEM>>>(Ah, Al, BLh, BLl, hl, N, K);
            gemm_mma_kernel<<<gg, 256, GEMM_SMEM>>>(Ah, Al, BRh, BRl, hr, N, K);

            gat_kernel<<<(N * 32 + 255) / 256, 256>>>(hl, hr, rowptr, csrsrc, at, bs, h, N);

            cudaMemsetAsync(bnsum, 0, 256 * sizeof(float), 0);
            cudaMemsetAsync(bnsq,  0, 256 * sizeof(float), 0);
            bn_stats_kernel<<<240, 256>>>(h, bnsum, bnsq, N);
            bn_final_kernel<<<1, 256>>>(bnsum, bnsq, bng + i * 256, bnb + i * 256,
                                        scale, shift, N);
            bn_apply_kernel<<<(N * 64 + 255) / 256, 256>>>(h, hn, scale, shift, N);

            in = hn;
            K = 256;
            wl = Wl2 + (size_t)i * 256 * 256;
            wr = Wr2 + (size_t)i * 256 * 256;
            at = att2 + i * 256;
            bs = b2 + i * 256;
        }

        classifier_kernel<<<(N * 32 + 255) / 256, 256>>>(hn, cW, cb,
                                                         out + (size_t)row_off * 2, N);
        row_off += N;
    }
}

// round 11
// speedup vs baseline: 1.6888x; 1.1655x over previous
#include <cuda_runtime.h>
#include <cuda_bf16.h>
#include <math.h>
#include <stdint.h>

// ---------------- static scratch (no runtime allocation allowed) ----------------
#define MAXN 50000
#define MAXE 400000

__device__ float g_hl[MAXN * 256];
__device__ float g_hr[MAXN * 256];
__device__ float g_h [MAXN * 256];
__device__ float g_hn[MAXN * 256];
__device__ __nv_bfloat16 g_Ah[MAXN * 256];
__device__ __nv_bfloat16 g_Al[MAXN * 256];
__device__ __nv_bfloat16 g_Bh[256 * 512];
__device__ __nv_bfloat16 g_Bl[256 * 512];
__device__ int   g_rowptr[MAXN + 1];
__device__ int   g_csrsrc[MAXE];
__device__ int   g_deg[MAXN];
__device__ int   g_cursor[MAXN];
__device__ int   g_bsum[64];
__device__ float g_bnsum[256];
__device__ float g_bnsq[256];
__device__ float g_scale[256];
__device__ float g_shift[256];

// ---------------- baseline-PTX helpers (no 'a'-suffix features) ----------------
__device__ __forceinline__ uint32_t smem_u32(const void* p) {
    uint32_t a;
    asm("{ .reg .u64 t; cvta.to.shared.u64 t, %1; cvt.u32.u64 %0, t; }" : "=r"(a) : "l"(p));
    return a;
}
__device__ __forceinline__ void cp_async16(uint32_t dst, const void* src) {
    asm volatile("cp.async.cg.shared.global [%0], [%1], 16;" :: "r"(dst), "l"(src));
}
__device__ __forceinline__ void cp_async16_pred(uint32_t dst, const void* src, bool pred) {
    int sz = pred ? 16 : 0;
    asm volatile("cp.async.cg.shared.global [%0], [%1], 16, %2;" :: "r"(dst), "l"(src), "r"(sz));
}
__device__ __forceinline__ void cp_commit() { asm volatile("cp.async.commit_group;" ::: "memory"); }
template <int N>
__device__ __forceinline__ void cp_wait() { asm volatile("cp.async.wait_group %0;" :: "n"(N) : "memory"); }

__device__ __forceinline__ void ldmat_x4(uint32_t addr, uint32_t& r0, uint32_t& r1,
                                         uint32_t& r2, uint32_t& r3) {
    asm volatile("ldmatrix.sync.aligned.m8n8.x4.shared.b16 {%0,%1,%2,%3}, [%4];"
                 : "=r"(r0), "=r"(r1), "=r"(r2), "=r"(r3) : "r"(addr));
}
__device__ __forceinline__ void ldmat_x4_t(uint32_t addr, uint32_t& r0, uint32_t& r1,
                                           uint32_t& r2, uint32_t& r3) {
    asm volatile("ldmatrix.sync.aligned.m8n8.x4.trans.shared.b16 {%0,%1,%2,%3}, [%4];"
                 : "=r"(r0), "=r"(r1), "=r"(r2), "=r"(r3) : "r"(addr));
}
__device__ __forceinline__ void mma_bf16(float& c0, float& c1, float& c2, float& c3,
                                         uint32_t a0, uint32_t a1, uint32_t a2, uint32_t a3,
                                         uint32_t b0, uint32_t b1) {
    asm volatile("mma.sync.aligned.m16n8k16.row.col.f32.bf16.bf16.f32 "
                 "{%0,%1,%2,%3}, {%4,%5,%6,%7}, {%8,%9}, {%0,%1,%2,%3};"
                 : "+f"(c0), "+f"(c1), "+f"(c2), "+f"(c3)
                 : "r"(a0), "r"(a1), "r"(a2), "r"(a3), "r"(b0), "r"(b1));
}

// ---------------- HMMA GEMM: [Cl|Cr][M,256] = A[M,K] @ Bcat[K,512], bf16 hi/lo split ----------------
// SMEM per stage: Ah[128][40]b16 @0, Al @10240, Bh[32][136]b16 @20480, Bl @29184
#define KC 32
#define A_STR 40
#define B_STR 136
#define S_AH 0
#define S_AL 10240
#define S_BH 20480
#define S_BL 29184
#define STAGE_B 37888
#define GEMM_SMEM (2 * STAGE_B)

__global__ __launch_bounds__(256) void gemm_mma_kernel(
    const __nv_bfloat16* __restrict__ Ah, const __nv_bfloat16* __restrict__ Al,
    const __nv_bfloat16* __restrict__ Bh, const __nv_bfloat16* __restrict__ Bl,
    float* __restrict__ Cl, float* __restrict__ Cr, int M, int K)
{
    extern __shared__ char smem[];
    const uint32_t sb = smem_u32(smem);
    const int tid  = threadIdx.x;
    const int lane = tid & 31;
    const int w    = tid >> 5;
    const int wm   = (w & 3) * 32;    // warp row block within 128
    const int wn   = (w >> 2) * 64;   // warp col block within 128
    const int bm   = blockIdx.y * 128;
    const int bn   = blockIdx.x * 128; // within 512 concat cols

    float* __restrict__ C = (bn < 256) ? Cl : Cr;
    const int cb0 = bn & 255;

    float acc[2][8][4];
#pragma unroll
    for (int i = 0; i < 2; i++)
#pragma unroll
        for (int j = 0; j < 8; j++)
#pragma unroll
            for (int k = 0; k < 4; k++) acc[i][j][k] = 0.f;

    const int nc = K >> 5;

    auto load_chunk = [&](int c) {
        const uint32_t st = sb + (c & 1) * STAGE_B;
        const int k0 = c * KC;
#pragma unroll
        for (int it = 0; it < 2; it++) {
            int lin = tid + it * 256;
            int row = lin >> 2, seg = lin & 3;
            bool p = (bm + row) < M;
            const char* gA = (const char*)(Ah + (size_t)(bm + row) * K + k0 + seg * 8);
            const char* gL = (const char*)(Al + (size_t)(bm + row) * K + k0 + seg * 8);
            cp_async16_pred(st + S_AH + row * (A_STR * 2) + seg * 16, gA, p);
            cp_async16_pred(st + S_AL + row * (A_STR * 2) + seg * 16, gL, p);
        }
#pragma unroll
        for (int it = 0; it < 2; it++) {
            int lin = tid + it * 256;
            int row = lin >> 4, seg = lin & 15;
            const char* gH = (const char*)(Bh + (size_t)(k0 + row) * 512 + bn + seg * 8);
            const char* gL = (const char*)(Bl + (size_t)(k0 + row) * 512 + bn + seg * 8);
            cp_async16(st + S_BH + row * (B_STR * 2) + seg * 16, gH);
            cp_async16(st + S_BL + row * (B_STR * 2) + seg * 16, gL);
        }
    };

    load_chunk(0);
    cp_commit();

    for (int c = 0; c < nc; c++) {
        if (c + 1 < nc) { load_chunk(c + 1); cp_commit(); cp_wait<1>(); }
        else            { cp_wait<0>(); }
        __syncthreads();

        const uint32_t st = sb + (c & 1) * STAGE_B;
#pragma unroll
        for (int ks = 0; ks < 2; ks++) {
            const int kk = ks * 16;
            uint32_t ah[2][4], al[2][4];
#pragma unroll
            for (int mt = 0; mt < 2; mt++) {
                uint32_t off = ((wm + mt * 16 + (lane & 15)) * A_STR + kk + (lane >> 4) * 8) * 2;
                ldmat_x4(st + S_AH + off, ah[mt][0], ah[mt][1], ah[mt][2], ah[mt][3]);
                ldmat_x4(st + S_AL + off, al[mt][0], al[mt][1], al[mt][2], al[mt][3]);
            }
            uint32_t bh[4][4], bl[4][4];
#pragma unroll
            for (int np = 0; np < 4; np++) {
                uint32_t off = ((kk + (lane & 15)) * B_STR + wn + np * 16 + (lane >> 4) * 8) * 2;
                ldmat_x4_t(st + S_BH + off, bh[np][0], bh[np][1], bh[np][2], bh[np][3]);
                ldmat_x4_t(st + S_BL + off, bl[np][0], bl[np][1], bl[np][2], bl[np][3]);
            }
#pragma unroll
            for (int mt = 0; mt < 2; mt++)
#pragma unroll
                for (int np = 0; np < 4; np++)
#pragma unroll
                    for (int half = 0; half < 2; half++) {
                        int nt = np * 2 + half;
                        float* a = acc[mt][nt];
                        uint32_t b0h = bh[np][half * 2], b1h = bh[np][half * 2 + 1];
                        uint32_t b0l = bl[np][half * 2], b1l = bl[np][half * 2 + 1];
                        mma_bf16(a[0], a[1], a[2], a[3],
                                 ah[mt][0], ah[mt][1], ah[mt][2], ah[mt][3], b0h, b1h);
                        mma_bf16(a[0], a[1], a[2], a[3],
                                 ah[mt][0], ah[mt][1], ah[mt][2], ah[mt][3], b0l, b1l);
                        mma_bf16(a[0], a[1], a[2], a[3],
                                 al[mt][0], al[mt][1], al[mt][2], al[mt][3], b0h, b1h);
                    }
        }
        __syncthreads();
    }

    const int g4 = lane >> 2, t4 = lane & 3;
#pragma unroll
    for (int mt = 0; mt < 2; mt++) {
        int r0 = bm + wm + mt * 16 + g4;
        int r1 = r0 + 8;
#pragma unroll
        for (int nt = 0; nt < 8; nt++) {
            int col = cb0 + wn + nt * 8 + t4 * 2;
            if (r0 < M) *(float2*)(C + (size_t)r0 * 256 + col) =
                make_float2(acc[mt][nt][0], acc[mt][nt][1]);
            if (r1 < M) *(float2*)(C + (size_t)r1 * 256 + col) =
                make_float2(acc[mt][nt][2], acc[mt][nt][3]);
        }
    }
}

// ---------------- fp32 -> bf16 hi/lo split (layer-1 activations) ----------------
__global__ void split_kernel(const float* __restrict__ in, __nv_bfloat16* __restrict__ hi,
                             __nv_bfloat16* __restrict__ lo, int n4) {
    int i = blockIdx.x * 256 + threadIdx.x;
    if (i >= n4) return;
    float4 v = ((const float4*)in)[i];
    __nv_bfloat16 h0 = __float2bfloat16(v.x), h1 = __float2bfloat16(v.y);
    __nv_bfloat16 h2 = __float2bfloat16(v.z), h3 = __float2bfloat16(v.w);
    __nv_bfloat16 l0 = __float2bfloat16(v.x - __bfloat162float(h0));
    __nv_bfloat16 l1 = __float2bfloat16(v.y - __bfloat162float(h1));
    __nv_bfloat16 l2 = __float2bfloat16(v.z - __bfloat162float(h2));
    __nv_bfloat16 l3 = __float2bfloat16(v.w - __bfloat162float(h3));
    ((__nv_bfloat162*)hi)[2 * i]     = __halves2bfloat162(h0, h1);
    ((__nv_bfloat162*)hi)[2 * i + 1] = __halves2bfloat162(h2, h3);
    ((__nv_bfloat162*)lo)[2 * i]     = __halves2bfloat162(l0, l1);
    ((__nv_bfloat162*)lo)[2 * i + 1] = __halves2bfloat162(l2, l3);
}

// ---------------- weight pack: Wl,Wr [K,256] -> Bcat [K,512] bf16 hi/lo ----------------
__global__ void pack_weights_kernel(const float* __restrict__ Wl, const float* __restrict__ Wr,
                                    __nv_bfloat16* __restrict__ th, __nv_bfloat16* __restrict__ tl,
                                    int K) {
    int idx = blockIdx.x * 256 + threadIdx.x;
    if (idx >= K * 512) return;
    int k = idx >> 9, c = idx & 511;
    float v = (c < 256) ? Wl[k * 256 + c] : Wr[k * 256 + (c - 256)];
    __nv_bfloat16 h = __float2bfloat16(v);
    th[idx] = h;
    tl[idx] = __float2bfloat16(v - __bfloat162float(h));
}

// ---------------- CSR build ----------------
__global__ void hist_kernel(const int* __restrict__ dst, int* __restrict__ deg, int E) {
    int e = blockIdx.x * 256 + threadIdx.x;
    if (e < E) atomicAdd(&deg[dst[e]], 1);
}

// block b sums deg[b*1024 .. b*1024+1024)
__global__ void scan_bsum_kernel(const int* __restrict__ deg, int* __restrict__ bsum, int N) {
    __shared__ int sh[256];
    int b = blockIdx.x, t = threadIdx.x;
    int s = 0;
    for (int j = t; j < 1024; j += 256) {
        int i = b * 1024 + j;
        if (i < N) s += deg[i];
    }
    sh[t] = s;
    __syncthreads();
    for (int off = 128; off > 0; off >>= 1) {
        if (t < off) sh[t] += sh[t + off];
        __syncthreads();
    }
    if (t == 0) bsum[b] = sh[0];
}

__global__ void scan_boff_kernel(int* __restrict__ bsum, int* __restrict__ rowptr,
                                 int nb, int N) {
    if (threadIdx.x == 0) {
        int acc = 0;
        for (int b = 0; b < nb; b++) { int v = bsum[b]; bsum[b] = acc; acc += v; }
        rowptr[N] = acc;
    }
}

__global__ void scan_final_kernel(const int* __restrict__ deg, const int* __restrict__ bsum,
                                  int* __restrict__ rowptr, int N) {
    __shared__ int sh[1024];
    int b = blockIdx.x, t = threadIdx.x;
    int i = b * 1024 + t;
    int v = (i < N) ? deg[i] : 0;
    sh[t] = v;
    __syncthreads();
    for (int off = 1; off < 1024; off <<= 1) {
        int u = (t >= off) ? sh[t - off] : 0;
        __syncthreads();
        sh[t] += u;
        __syncthreads();
    }
    if (i < N) rowptr[i] = bsum[b] + sh[t] - v;
}

__global__ void scatter_kernel(const int* __restrict__ src, const int* __restrict__ dst,
                               const int* __restrict__ rowptr, int* __restrict__ cursor,
                               int* __restrict__ csrsrc, int E) {
    int e = blockIdx.x * 256 + threadIdx.x;
    if (e < E) {
        int d = dst[e];
        int pos = atomicAdd(&cursor[d], 1);
        csrsrc[rowptr[d] + pos] = src[e];
    }
}

// ---------------- GATv2 aggregate: one warp per dst node, online softmax ----------------
__global__ __launch_bounds__(256) void gat_kernel(
    const float* __restrict__ hl, const float* __restrict__ hr,
    const int* __restrict__ rowptr, const int* __restrict__ csrsrc,
    const float* __restrict__ att, const float* __restrict__ bias,
    float* __restrict__ out, int N)
{
    int warp = (blockIdx.x * blockDim.x + threadIdx.x) >> 5;
    if (warp >= N) return;
    int lane = threadIdx.x & 31;
    int d = warp;
    int base = lane * 8;

    float4 at0 = *(const float4*)(att + base);
    float4 at1 = *(const float4*)(att + base + 4);
    float atv[8] = {at0.x, at0.y, at0.z, at0.w, at1.x, at1.y, at1.z, at1.w};

    const float* hrp = hr + (size_t)d * 256 + base;
    float4 r0 = *(const float4*)hrp;
    float4 r1 = *(const float4*)(hrp + 4);
    float hrv[8] = {r0.x, r0.y, r0.z, r0.w, r1.x, r1.y, r1.z, r1.w};

    float m = -1.0e30f, den = 0.f;
    float acc[8] = {0.f, 0.f, 0.f, 0.f, 0.f, 0.f, 0.f, 0.f};

    int e0 = rowptr[d], e1 = rowptr[d + 1];
    for (int e = e0 - 1; e < e1; e++) {          // e == e0-1 -> self loop
        int s = (e < e0) ? d : csrsrc[e];
        const float* hp = hl + (size_t)s * 256 + base;
        float4 h0 = *(const float4*)hp;
        float4 h1 = *(const float4*)(hp + 4);
        float hv[8] = {h0.x, h0.y, h0.z, h0.w, h1.x, h1.y, h1.z, h1.w};

        float p = 0.f;
#pragma unroll
        for (int j = 0; j < 8; j++) {
            float v = hv[j] + hrv[j];
            v = (v > 0.f) ? v : 0.2f * v;
            p += v * atv[j];
        }
        p += __shfl_xor_sync(0xffffffffu, p, 1);
        p += __shfl_xor_sync(0xffffffffu, p, 2);
        p += __shfl_xor_sync(0xffffffffu, p, 4);

        float nm = fmaxf(m, p);
        float f  = __expf(m - nm);
        float wv = __expf(p - nm);
        den = den * f + wv;
        m = nm;
#pragma unroll
        for (int j = 0; j < 8; j++) acc[j] = acc[j] * f + wv * hv[j];
    }

    float inv = 1.f / (den + 1e-16f);
    float* op = out + (size_t)d * 256 + base;
    float4 o0, o1;
    o0.x = acc[0] * inv + bias[base + 0];
    o0.y = acc[1] * inv + bias[base + 1];
    o0.z = acc[2] * inv + bias[base + 2];
    o0.w = acc[3] * inv + bias[base + 3];
    o1.x = acc[4] * inv + bias[base + 4];
    o1.y = acc[5] * inv + bias[base + 5];
    o1.z = acc[6] * inv + bias[base + 6];
    o1.w = acc[7] * inv + bias[base + 7];
    *(float4*)op       = o0;
    *(float4*)(op + 4) = o1;
}

// ---------------- BatchNorm ----------------
__global__ void bn_stats_kernel(const float* __restrict__ x,
                                float* __restrict__ bnsum, float* __restrict__ bnsq, int N) {
    int c = threadIdx.x;
    float s = 0.f, q = 0.f;
    for (int r = blockIdx.x; r < N; r += gridDim.x) {
        float v = x[(size_t)r * 256 + c];
        s += v;
        q += v * v;
    }
    atomicAdd(&bnsum[c], s);
    atomicAdd(&bnsq[c], q);
}

__global__ void bn_final_kernel(const float* __restrict__ bnsum, const float* __restrict__ bnsq,
                                const float* __restrict__ g, const float* __restrict__ b,
                                float* __restrict__ scale, float* __restrict__ shift, int N) {
    int c = threadIdx.x;
    float invn = 1.f / (float)N;
    float mean = bnsum[c] * invn;
    float var  = bnsq[c] * invn - mean * mean;
    float sc   = g[c] * rsqrtf(var + 1e-5f);
    scale[c] = sc;
    shift[c] = b[c] - mean * sc;
}

// bn + leaky-relu; optionally also emit bf16 hi/lo split for the next GEMM
__global__ void bn_apply_kernel(const float* __restrict__ in, float* __restrict__ outp,
                                __nv_bfloat16* __restrict__ oh, __nv_bfloat16* __restrict__ ol,
                                const float* __restrict__ scale, const float* __restrict__ shift,
                                int N, int do_split) {
    int i = blockIdx.x * 256 + threadIdx.x;
    if (i >= N * 64) return;
    int c = (i & 63) * 4;
    float4 v  = *(const float4*)(in + (size_t)i * 4);
    float4 sc = *(const float4*)(scale + c);
    float4 sh = *(const float4*)(shift + c);
    float a0 = v.x * sc.x + sh.x;
    float a1 = v.y * sc.y + sh.y;
    float a2 = v.z * sc.z + sh.z;
    float a3 = v.w * sc.w + sh.w;
    float4 o;
    o.x = (a0 > 0.f) ? a0 : 0.01f * a0;
    o.y = (a1 > 0.f) ? a1 : 0.01f * a1;
    o.z = (a2 > 0.f) ? a2 : 0.01f * a2;
    o.w = (a3 > 0.f) ? a3 : 0.01f * a3;
    *(float4*)(outp + (size_t)i * 4) = o;
    if (do_split) {
        __nv_bfloat16 h0 = __float2bfloat16(o.x), h1 = __float2bfloat16(o.y);
        __nv_bfloat16 h2 = __float2bfloat16(o.z), h3 = __float2bfloat16(o.w);
        __nv_bfloat16 l0 = __float2bfloat16(o.x - __bfloat162float(h0));
        __nv_bfloat16 l1 = __float2bfloat16(o.y - __bfloat162float(h1));
        __nv_bfloat16 l2 = __float2bfloat16(o.z - __bfloat162float(h2));
        __nv_bfloat16 l3 = __float2bfloat16(o.w - __bfloat162float(h3));
        ((__nv_bfloat162*)oh)[2 * i]     = __halves2bfloat162(h0, h1);
        ((__nv_bfloat162*)oh)[2 * i + 1] = __halves2bfloat162(h2, h3);
        ((__nv_bfloat162*)ol)[2 * i]     = __halves2bfloat162(l0, l1);
        ((__nv_bfloat162*)ol)[2 * i + 1] = __halves2bfloat162(l2, l3);
    }
}

// ---------------- Classifier ----------------
__global__ __launch_bounds__(256) void classifier_kernel(
    const float* __restrict__ h, const float* __restrict__ cW,
    const float* __restrict__ cb, float* __restrict__ outp, int N)
{
    int warp = (blockIdx.x * blockDim.x + threadIdx.x) >> 5;
    if (warp >= N) return;
    int lane = threadIdx.x & 31;

    const float* hp = h + (size_t)warp * 256 + lane * 8;
    float4 h0 = *(const float4*)hp;
    float4 h1 = *(const float4*)(hp + 4);
    float hv[8] = {h0.x, h0.y, h0.z, h0.w, h1.x, h1.y, h1.z, h1.w};

    const float* wp = cW + lane * 16;
    float4 w0 = *(const float4*)(wp + 0);
    float4 w1 = *(const float4*)(wp + 4);
    float4 w2 = *(const float4*)(wp + 8);
    float4 w3 = *(const float4*)(wp + 12);
    float wv[16] = {w0.x, w0.y, w0.z, w0.w, w1.x, w1.y, w1.z, w1.w,
                    w2.x, w2.y, w2.z, w2.w, w3.x, w3.y, w3.z, w3.w};

    float c0 = 0.f, c1 = 0.f;
#pragma unroll
    for (int j = 0; j < 8; j++) {
        c0 += hv[j] * wv[2 * j];
        c1 += hv[j] * wv[2 * j + 1];
    }
#pragma unroll
    for (int off = 16; off > 0; off >>= 1) {
        c0 += __shfl_xor_sync(0xffffffffu, c0, off);
        c1 += __shfl_xor_sync(0xffffffffu, c1, off);
    }
    if (lane == 0) {
        outp[(size_t)warp * 2 + 0] = c0 + cb[0];
        outp[(size_t)warp * 2 + 1] = c1 + cb[1];
    }
}

// ---------------- launch ----------------
extern "C" void kernel_launch(void* const* d_in, const int* in_sizes, int n_in,
                              void* d_out, int out_size) {
    const float* x[3];
    const int*   ei[3];
    for (int i = 0; i < 3; i++) {
        x[i]  = (const float*)d_in[i];
        ei[i] = (const int*)d_in[3 + i];
    }
    const float* Wl1  = (const float*)d_in[6];
    const float* Wr1  = (const float*)d_in[7];
    const float* att1 = (const float*)d_in[8];
    const float* b1   = (const float*)d_in[9];
    const float* Wl2  = (const float*)d_in[10];
    const float* Wr2  = (const float*)d_in[11];
    const float* att2 = (const float*)d_in[12];
    const float* b2   = (const float*)d_in[13];
    const float* bng  = (const float*)d_in[14];
    const float* bnb  = (const float*)d_in[15];
    const float* cW   = (const float*)d_in[16];
    const float* cb   = (const float*)d_in[17];
    float* out = (float*)d_out;

    float *hl, *hr, *h, *hn, *bnsum, *bnsq, *scale, *shift;
    __nv_bfloat16 *Ah, *Al, *Bh, *Bl;
    int *rowptr, *csrsrc, *deg, *cursor, *bsum;
    cudaGetSymbolAddress((void**)&hl,     g_hl);
    cudaGetSymbolAddress((void**)&hr,     g_hr);
    cudaGetSymbolAddress((void**)&h,      g_h);
    cudaGetSymbolAddress((void**)&hn,     g_hn);
    cudaGetSymbolAddress((void**)&Ah,     g_Ah);
    cudaGetSymbolAddress((void**)&Al,     g_Al);
    cudaGetSymbolAddress((void**)&Bh,     g_Bh);
    cudaGetSymbolAddress((void**)&Bl,     g_Bl);
    cudaGetSymbolAddress((void**)&rowptr, g_rowptr);
    cudaGetSymbolAddress((void**)&csrsrc, g_csrsrc);
    cudaGetSymbolAddress((void**)&deg,    g_deg);
    cudaGetSymbolAddress((void**)&cursor, g_cursor);
    cudaGetSymbolAddress((void**)&bsum,   g_bsum);
    cudaGetSymbolAddress((void**)&bnsum,  g_bnsum);
    cudaGetSymbolAddress((void**)&bnsq,   g_bnsq);
    cudaGetSymbolAddress((void**)&scale,  g_scale);
    cudaGetSymbolAddress((void**)&shift,  g_shift);

    cudaFuncSetAttribute(gemm_mma_kernel,
                         cudaFuncAttributeMaxDynamicSharedMemorySize, GEMM_SMEM);

    int row_off = 0;
    for (int i = 0; i < 3; i++) {
        int N = in_sizes[i] / 128;
        int E = in_sizes[3 + i] / 2;
        const int* src = ei[i];
        const int* dst = ei[i] + E;

        // CSR build (shared by both GAT layers)
        int nb = (N + 1023) / 1024;
        cudaMemsetAsync(deg, 0, N * sizeof(int), 0);
        hist_kernel<<<(E + 255) / 256, 256>>>(dst, deg, E);
        scan_bsum_kernel<<<nb, 256>>>(deg, bsum, N);
        scan_boff_kernel<<<1, 32>>>(bsum, rowptr, nb, N);
        scan_final_kernel<<<nb, 1024>>>(deg, bsum, rowptr, N);
        cudaMemsetAsync(cursor, 0, N * sizeof(int), 0);
        scatter_kernel<<<(E + 255) / 256, 256>>>(src, dst, rowptr, cursor, csrsrc, E);

        // layer-1 input split (x)
        split_kernel<<<(N * 32 + 255) / 256, 256>>>(x[i], Ah, Al, N * 32);

        int K = 128;
        const float* wl = Wl1 + (size_t)i * 128 * 256;
        const float* wr = Wr1 + (size_t)i * 128 * 256;
        const float* at = att1 + i * 256;
        const float* bs = b1 + i * 256;

        for (int layer = 0; layer < 2; layer++) {
            pack_weights_kernel<<<(K * 512 + 255) / 256, 256>>>(wl, wr, Bh, Bl, K);

            dim3 gg(4, (N + 127) / 128);
            gemm_mma_kernel<<<gg, 256, GEMM_SMEM>>>(Ah, Al, Bh, Bl, hl, hr, N, K);

            gat_kernel<<<(N * 32 + 255) / 256, 256>>>(hl, hr, rowptr, csrsrc, at, bs, h, N);

            cudaMemsetAsync(bnsum, 0, 256 * sizeof(float), 0);
            cudaMemsetAsync(bnsq,  0, 256 * sizeof(float), 0);
            bn_stats_kernel<<<240, 256>>>(h, bnsum, bnsq, N);
            bn_final_kernel<<<1, 256>>>(bnsum, bnsq, bng + i * 256, bnb + i * 256,
                                        scale, shift, N);
            bn_apply_kernel<<<(N * 64 + 255) / 256, 256>>>(
                h, hn, Ah, Al, scale, shift, N, layer == 0 ? 1 : 0);

            K = 256;
            wl = Wl2 + (size_t)i * 256 * 256;
            wr = Wr2 + (size_t)i * 256 * 256;
            at = att2 + i * 256;
            bs = b2 + i * 256;
        }

        classifier_kernel<<<(N * 32 + 255) / 256, 256>>>(hn, cW, cb,
                                                         out + (size_t)row_off * 2, N);
        row_off += N;
    }
}

// round 12
// speedup vs baseline: 1.7576x; 1.0407x over previous
#include <cuda_runtime.h>
#include <cuda_bf16.h>
#include <math.h>
#include <stdint.h>

// ---------------- static scratch (no runtime allocation allowed) ----------------
#define MAXN 50000
#define NPADMAX (3 * 50048)          // per-type padded to 128 rows
#define MAXET (3 * 400000)

__device__ float g_hl[NPADMAX * 256];
__device__ float g_hr[NPADMAX * 256];
__device__ float g_h [NPADMAX * 256];
__device__ float g_hn[NPADMAX * 256];
__device__ __nv_bfloat16 g_Ah[NPADMAX * 256];
__device__ __nv_bfloat16 g_Al[NPADMAX * 256];
__device__ __nv_bfloat16 g_Bh[3 * (128 + 256) * 512];
__device__ __nv_bfloat16 g_Bl[3 * (128 + 256) * 512];
__device__ int   g_rowptr[NPADMAX + 1];
__device__ int   g_csrsrc[MAXET];
__device__ int   g_deg[NPADMAX];
__device__ int   g_cursor[NPADMAX];
__device__ int   g_bsum[256];
__device__ float g_bnsum[768];
__device__ float g_bnsq[768];
__device__ float g_scale[768];
__device__ float g_shift[768];

#define L2_WOFF (3 * 128 * 512)      // offset of layer-2 weights inside g_Bh/g_Bl

// ---------------- baseline-PTX helpers (no 'a'-suffix features) ----------------
__device__ __forceinline__ uint32_t smem_u32(const void* p) {
    uint32_t a;
    asm("{ .reg .u64 t; cvta.to.shared.u64 t, %1; cvt.u32.u64 %0, t; }" : "=r"(a) : "l"(p));
    return a;
}
__device__ __forceinline__ void cp_async16(uint32_t dst, const void* src) {
    asm volatile("cp.async.cg.shared.global [%0], [%1], 16;" :: "r"(dst), "l"(src));
}
__device__ __forceinline__ void cp_commit() { asm volatile("cp.async.commit_group;" ::: "memory"); }
template <int N>
__device__ __forceinline__ void cp_wait() { asm volatile("cp.async.wait_group %0;" :: "n"(N) : "memory"); }

__device__ __forceinline__ void ldmat_x4(uint32_t addr, uint32_t& r0, uint32_t& r1,
                                         uint32_t& r2, uint32_t& r3) {
    asm volatile("ldmatrix.sync.aligned.m8n8.x4.shared.b16 {%0,%1,%2,%3}, [%4];"
                 : "=r"(r0), "=r"(r1), "=r"(r2), "=r"(r3) : "r"(addr));
}
__device__ __forceinline__ void ldmat_x4_t(uint32_t addr, uint32_t& r0, uint32_t& r1,
                                           uint32_t& r2, uint32_t& r3) {
    asm volatile("ldmatrix.sync.aligned.m8n8.x4.trans.shared.b16 {%0,%1,%2,%3}, [%4];"
                 : "=r"(r0), "=r"(r1), "=r"(r2), "=r"(r3) : "r"(addr));
}
__device__ __forceinline__ void mma_bf16(float& c0, float& c1, float& c2, float& c3,
                                         uint32_t a0, uint32_t a1, uint32_t a2, uint32_t a3,
                                         uint32_t b0, uint32_t b1) {
    asm volatile("mma.sync.aligned.m16n8k16.row.col.f32.bf16.bf16.f32 "
                 "{%0,%1,%2,%3}, {%4,%5,%6,%7}, {%8,%9}, {%0,%1,%2,%3};"
                 : "+f"(c0), "+f"(c1), "+f"(c2), "+f"(c3)
                 : "r"(a0), "r"(a1), "r"(a2), "r"(a3), "r"(b0), "r"(b1));
}

// ---------------- HMMA GEMM: [hl|hr][M,256] = A[Mpad,K] @ Bcat_type[K,512] ----------------
// SMEM per stage: Ah[128][40]b16 @0, Al @10240, Bh[32][136]b16 @20480, Bl @29184
#define KC 32
#define A_STR 40
#define B_STR 136
#define S_AH 0
#define S_AL 10240
#define S_BH 20480
#define S_BL 29184
#define STAGE_B 37888
#define GEMM_SMEM (2 * STAGE_B)

__global__ __launch_bounds__(256) void gemm_mma_kernel(
    const __nv_bfloat16* __restrict__ Ah, const __nv_bfloat16* __restrict__ Al,
    const __nv_bfloat16* __restrict__ BhAll, const __nv_bfloat16* __restrict__ BlAll,
    float* __restrict__ Cl, float* __restrict__ Cr,
    int P1, int P2, int N0, int N1, int N2, int K, int wbase)
{
    extern __shared__ char smem[];
    const uint32_t sb = smem_u32(smem);
    const int tid  = threadIdx.x;
    const int lane = tid & 31;
    const int w    = tid >> 5;
    const int wm   = (w & 3) * 32;
    const int wn   = (w >> 2) * 64;
    const int bm   = blockIdx.y * 128;
    const int bn   = blockIdx.x * 128;   // within 512 concat cols

    const int t  = (bm >= P2) ? 2 : (bm >= P1 ? 1 : 0);
    const int Pt = (t == 2) ? P2 : (t == 1 ? P1 : 0);
    const int Nt = (t == 2) ? N2 : (t == 1 ? N1 : N0);
    const __nv_bfloat16* __restrict__ Bh = BhAll + wbase + (size_t)t * K * 512;
    const __nv_bfloat16* __restrict__ Bl = BlAll + wbase + (size_t)t * K * 512;

    float* __restrict__ C = (bn < 256) ? Cl : Cr;
    const int cb0 = bn & 255;

    float acc[2][8][4];
#pragma unroll
    for (int i = 0; i < 2; i++)
#pragma unroll
        for (int j = 0; j < 8; j++)
#pragma unroll
            for (int k = 0; k < 4; k++) acc[i][j][k] = 0.f;

    const int nc = K >> 5;

    auto load_chunk = [&](int c) {
        const uint32_t st = sb + (c & 1) * STAGE_B;
        const int k0 = c * KC;
#pragma unroll
        for (int it = 0; it < 2; it++) {
            int lin = tid + it * 256;
            int row = lin >> 2, seg = lin & 3;
            const char* gA = (const char*)(Ah + (size_t)(bm + row) * K + k0 + seg * 8);
            const char* gL = (const char*)(Al + (size_t)(bm + row) * K + k0 + seg * 8);
            cp_async16(st + S_AH + row * (A_STR * 2) + seg * 16, gA);
            cp_async16(st + S_AL + row * (A_STR * 2) + seg * 16, gL);
        }
#pragma unroll
        for (int it = 0; it < 2; it++) {
            int lin = tid + it * 256;
            int row = lin >> 4, seg = lin & 15;
            const char* gH = (const char*)(Bh + (size_t)(k0 + row) * 512 + bn + seg * 8);
            const char* gL = (const char*)(Bl + (size_t)(k0 + row) * 512 + bn + seg * 8);
            cp_async16(st + S_BH + row * (B_STR * 2) + seg * 16, gH);
            cp_async16(st + S_BL + row * (B_STR * 2) + seg * 16, gL);
        }
    };

    load_chunk(0);
    cp_commit();

    for (int c = 0; c < nc; c++) {
        if (c + 1 < nc) { load_chunk(c + 1); cp_commit(); cp_wait<1>(); }
        else            { cp_wait<0>(); }
        __syncthreads();

        const uint32_t st = sb + (c & 1) * STAGE_B;
#pragma unroll
        for (int ks = 0; ks < 2; ks++) {
            const int kk = ks * 16;
            uint32_t ah[2][4], al[2][4];
#pragma unroll
            for (int mt = 0; mt < 2; mt++) {
                uint32_t off = ((wm + mt * 16 + (lane & 15)) * A_STR + kk + (lane >> 4) * 8) * 2;
                ldmat_x4(st + S_AH + off, ah[mt][0], ah[mt][1], ah[mt][2], ah[mt][3]);
                ldmat_x4(st + S_AL + off, al[mt][0], al[mt][1], al[mt][2], al[mt][3]);
            }
            uint32_t bh[4][4], bl[4][4];
#pragma unroll
            for (int np = 0; np < 4; np++) {
                uint32_t off = ((kk + (lane & 15)) * B_STR + wn + np * 16 + (lane >> 4) * 8) * 2;
                ldmat_x4_t(st + S_BH + off, bh[np][0], bh[np][1], bh[np][2], bh[np][3]);
                ldmat_x4_t(st + S_BL + off, bl[np][0], bl[np][1], bl[np][2], bl[np][3]);
            }
#pragma unroll
            for (int mt = 0; mt < 2; mt++)
#pragma unroll
                for (int np = 0; np < 4; np++)
#pragma unroll
                    for (int half = 0; half < 2; half++) {
                        int nt = np * 2 + half;
                        float* a = acc[mt][nt];
                        uint32_t b0h = bh[np][half * 2], b1h = bh[np][half * 2 + 1];
                        uint32_t b0l = bl[np][half * 2], b1l = bl[np][half * 2 + 1];
                        mma_bf16(a[0], a[1], a[2], a[3],
                                 ah[mt][0], ah[mt][1], ah[mt][2], ah[mt][3], b0h, b1h);
                        mma_bf16(a[0], a[1], a[2], a[3],
                                 ah[mt][0], ah[mt][1], ah[mt][2], ah[mt][3], b0l, b1l);
                        mma_bf16(a[0], a[1], a[2], a[3],
                                 al[mt][0], al[mt][1], al[mt][2], al[mt][3], b0h, b1h);
                    }
        }
        __syncthreads();
    }

    const int g4 = lane >> 2, t4 = lane & 3;
#pragma unroll
    for (int mt = 0; mt < 2; mt++) {
        int r0 = bm + wm + mt * 16 + g4;
        int r1 = r0 + 8;
#pragma unroll
        for (int nt = 0; nt < 8; nt++) {
            int col = cb0 + wn + nt * 8 + t4 * 2;
            if (r0 - Pt < Nt) *(float2*)(C + (size_t)r0 * 256 + col) =
                make_float2(acc[mt][nt][0], acc[mt][nt][1]);
            if (r1 - Pt < Nt) *(float2*)(C + (size_t)r1 * 256 + col) =
                make_float2(acc[mt][nt][2], acc[mt][nt][3]);
        }
    }
}

// ---------------- layer-1 split: x (3 ptrs) -> Ah/Al [NPAD,128], pads zeroed ----------------
__global__ void split_x_kernel(const float* __restrict__ x0, const float* __restrict__ x1,
                               const float* __restrict__ x2,
                               __nv_bfloat16* __restrict__ hi, __nv_bfloat16* __restrict__ lo,
                               int P1, int P2, int N0, int N1, int N2, int NPAD) {
    int i = blockIdx.x * 256 + threadIdx.x;      // float4 index over NPAD*128
    if (i >= NPAD * 32) return;
    int row = i >> 5, q = i & 31;
    int t  = (row >= P2) ? 2 : (row >= P1 ? 1 : 0);
    int Pt = (t == 2) ? P2 : (t == 1 ? P1 : 0);
    int Nt = (t == 2) ? N2 : (t == 1 ? N1 : N0);
    const float* xp = (t == 2) ? x2 : (t == 1 ? x1 : x0);
    int lr = row - Pt;
    float4 v = make_float4(0.f, 0.f, 0.f, 0.f);
    if (lr < Nt) v = ((const float4*)xp)[lr * 32 + q];
    __nv_bfloat16 h0 = __float2bfloat16(v.x), h1 = __float2bfloat16(v.y);
    __nv_bfloat16 h2 = __float2bfloat16(v.z), h3 = __float2bfloat16(v.w);
    __nv_bfloat16 l0 = __float2bfloat16(v.x - __bfloat162float(h0));
    __nv_bfloat16 l1 = __float2bfloat16(v.y - __bfloat162float(h1));
    __nv_bfloat16 l2 = __float2bfloat16(v.z - __bfloat162float(h2));
    __nv_bfloat16 l3 = __float2bfloat16(v.w - __bfloat162float(h3));
    ((__nv_bfloat162*)hi)[2 * i]     = __halves2bfloat162(h0, h1);
    ((__nv_bfloat162*)hi)[2 * i + 1] = __halves2bfloat162(h2, h3);
    ((__nv_bfloat162*)lo)[2 * i]     = __halves2bfloat162(l0, l1);
    ((__nv_bfloat162*)lo)[2 * i + 1] = __halves2bfloat162(l2, l3);
}

// ---------------- pack ALL weights (both layers, 3 types) -> Bcat hi/lo ----------------
__global__ void pack_weights_kernel(const float* __restrict__ Wl1, const float* __restrict__ Wr1,
                                    const float* __restrict__ Wl2, const float* __restrict__ Wr2,
                                    __nv_bfloat16* __restrict__ th, __nv_bfloat16* __restrict__ tl) {
    int idx = blockIdx.x * 256 + threadIdx.x;
    const int L1 = 3 * 128 * 512;
    const int TOT = L1 + 3 * 256 * 512;
    if (idx >= TOT) return;
    float v;
    if (idx < L1) {
        int t = idx / (128 * 512), rem = idx % (128 * 512);
        int k = rem >> 9, c = rem & 511;
        v = (c < 256) ? Wl1[(size_t)t * 128 * 256 + k * 256 + c]
                      : Wr1[(size_t)t * 128 * 256 + k * 256 + (c - 256)];
    } else {
        int j = idx - L1;
        int t = j / (256 * 512), rem = j % (256 * 512);
        int k = rem >> 9, c = rem & 511;
        v = (c < 256) ? Wl2[(size_t)t * 256 * 256 + k * 256 + c]
                      : Wr2[(size_t)t * 256 * 256 + k * 256 + (c - 256)];
    }
    __nv_bfloat16 h = __float2bfloat16(v);
    th[idx] = h;
    tl[idx] = __float2bfloat16(v - __bfloat162float(h));
}

// ---------------- CSR build (all types, global padded node ids) ----------------
__global__ void hist_kernel(const int* __restrict__ d0, const int* __restrict__ d1,
                            const int* __restrict__ d2, int* __restrict__ deg,
                            int E0, int E1, int E2, int P1, int P2) {
    int e = blockIdx.x * 256 + threadIdx.x;
    int dv;
    if (e < E0) dv = d0[e];
    else if (e < E0 + E1) dv = d1[e - E0] + P1;
    else if (e < E0 + E1 + E2) dv = d2[e - E0 - E1] + P2;
    else return;
    atomicAdd(&deg[dv], 1);
}

__global__ void scan_bsum_kernel(const int* __restrict__ deg, int* __restrict__ bsum, int N) {
    __shared__ int sh[256];
    int b = blockIdx.x, t = threadIdx.x;
    int s = 0;
    for (int j = t; j < 1024; j += 256) {
        int i = b * 1024 + j;
        if (i < N) s += deg[i];
    }
    sh[t] = s;
    __syncthreads();
    for (int off = 128; off > 0; off >>= 1) {
        if (t < off) sh[t] += sh[t + off];
        __syncthreads();
    }
    if (t == 0) bsum[b] = sh[0];
}

__global__ void scan_boff_kernel(int* __restrict__ bsum, int* __restrict__ rowptr,
                                 int nb, int N) {
    if (threadIdx.x == 0) {
        int acc = 0;
        for (int b = 0; b < nb; b++) { int v = bsum[b]; bsum[b] = acc; acc += v; }
        rowptr[N] = acc;
    }
}

__global__ void scan_final_kernel(const int* __restrict__ deg, const int* __restrict__ bsum,
                                  int* __restrict__ rowptr, int N) {
    __shared__ int sh[1024];
    int b = blockIdx.x, t = threadIdx.x;
    int i = b * 1024 + t;
    int v = (i < N) ? deg[i] : 0;
    sh[t] = v;
    __syncthreads();
    for (int off = 1; off < 1024; off <<= 1) {
        int u = (t >= off) ? sh[t - off] : 0;
        __syncthreads();
        sh[t] += u;
        __syncthreads();
    }
    if (i < N) rowptr[i] = bsum[b] + sh[t] - v;
}

__global__ void scatter_kernel(const int* __restrict__ s0, const int* __restrict__ d0,
                               const int* __restrict__ s1, const int* __restrict__ d1,
                               const int* __restrict__ s2, const int* __restrict__ d2,
                               const int* __restrict__ rowptr, int* __restrict__ cursor,
                               int* __restrict__ csrsrc,
                               int E0, int E1, int E2, int P1, int P2) {
    int e = blockIdx.x * 256 + threadIdx.x;
    int sv, dv;
    if (e < E0)                { sv = s0[e];            dv = d0[e]; }
    else if (e < E0 + E1)      { sv = s1[e - E0] + P1;  dv = d1[e - E0] + P1; }
    else if (e < E0 + E1 + E2) { sv = s2[e - E0 - E1] + P2; dv = d2[e - E0 - E1] + P2; }
    else return;
    int pos = atomicAdd(&cursor[dv], 1);
    csrsrc[rowptr[dv] + pos] = sv;
}

// ---------------- GATv2 aggregate (all types): one warp per dst node ----------------
__global__ __launch_bounds__(256) void gat_kernel(
    const float* __restrict__ hl, const float* __restrict__ hr,
    const int* __restrict__ rowptr, const int* __restrict__ csrsrc,
    const float* __restrict__ attAll, const float* __restrict__ biasAll,
    float* __restrict__ out, int P1, int P2, int N0, int N1, int N2, int NPAD)
{
    int d = (blockIdx.x * blockDim.x + threadIdx.x) >> 5;
    if (d >= NPAD) return;
    int t  = (d >= P2) ? 2 : (d >= P1 ? 1 : 0);
    int Pt = (t == 2) ? P2 : (t == 1 ? P1 : 0);
    int Nt = (t == 2) ? N2 : (t == 1 ? N1 : N0);
    if (d - Pt >= Nt) return;                     // pad node
    int lane = threadIdx.x & 31;
    int base = lane * 8;
    const float* att  = attAll + t * 256;
    const float* bias = biasAll + t * 256;

    float4 at0 = *(const float4*)(att + base);
    float4 at1 = *(const float4*)(att + base + 4);
    float atv[8] = {at0.x, at0.y, at0.z, at0.w, at1.x, at1.y, at1.z, at1.w};

    const float* hrp = hr + (size_t)d * 256 + base;
    float4 r0 = *(const float4*)hrp;
    float4 r1 = *(const float4*)(hrp + 4);
    float hrv[8] = {r0.x, r0.y, r0.z, r0.w, r1.x, r1.y, r1.z, r1.w};

    float m = -1.0e30f, den = 0.f;
    float acc[8] = {0.f, 0.f, 0.f, 0.f, 0.f, 0.f, 0.f, 0.f};

    int e0 = rowptr[d], e1 = rowptr[d + 1];
    for (int e = e0 - 1; e < e1; e++) {          // e == e0-1 -> self loop
        int s = (e < e0) ? d : csrsrc[e];
        const float* hp = hl + (size_t)s * 256 + base;
        float4 h0 = *(const float4*)hp;
        float4 h1 = *(const float4*)(hp + 4);
        float hv[8] = {h0.x, h0.y, h0.z, h0.w, h1.x, h1.y, h1.z, h1.w};

        float p = 0.f;
#pragma unroll
        for (int j = 0; j < 8; j++) {
            float v = hv[j] + hrv[j];
            v = (v > 0.f) ? v : 0.2f * v;
            p += v * atv[j];
        }
        p += __shfl_xor_sync(0xffffffffu, p, 1);
        p += __shfl_xor_sync(0xffffffffu, p, 2);
        p += __shfl_xor_sync(0xffffffffu, p, 4);

        float nm = fmaxf(m, p);
        float f  = __expf(m - nm);
        float wv = __expf(p - nm);
        den = den * f + wv;
        m = nm;
#pragma unroll
        for (int j = 0; j < 8; j++) acc[j] = acc[j] * f + wv * hv[j];
    }

    float inv = 1.f / (den + 1e-16f);
    float* op = out + (size_t)d * 256 + base;
    float4 o0, o1;
    o0.x = acc[0] * inv + bias[base + 0];
    o0.y = acc[1] * inv + bias[base + 1];
    o0.z = acc[2] * inv + bias[base + 2];
    o0.w = acc[3] * inv + bias[base + 3];
    o1.x = acc[4] * inv + bias[base + 4];
    o1.y = acc[5] * inv + bias[base + 5];
    o1.z = acc[6] * inv + bias[base + 6];
    o1.w = acc[7] * inv + bias[base + 7];
    *(float4*)op       = o0;
    *(float4*)(op + 4) = o1;
}

// ---------------- BatchNorm (per-type stats, grid.y = type) ----------------
__global__ void bn_stats_kernel(const float* __restrict__ x,
                                float* __restrict__ bnsum, float* __restrict__ bnsq,
                                int P1, int P2, int N0, int N1, int N2) {
    int t = blockIdx.y;
    int Pt = (t == 2) ? P2 : (t == 1 ? P1 : 0);
    int Nt = (t == 2) ? N2 : (t == 1 ? N1 : N0);
    int c = threadIdx.x;
    float s = 0.f, q = 0.f;
    for (int r = blockIdx.x; r < Nt; r += gridDim.x) {
        float v = x[(size_t)(Pt + r) * 256 + c];
        s += v;
        q += v * v;
    }
    atomicAdd(&bnsum[t * 256 + c], s);
    atomicAdd(&bnsq[t * 256 + c], q);
}

__global__ void bn_final_kernel(const float* __restrict__ bnsum, const float* __restrict__ bnsq,
                                const float* __restrict__ g, const float* __restrict__ b,
                                float* __restrict__ scale, float* __restrict__ shift,
                                int N0, int N1, int N2) {
    int c = threadIdx.x + blockIdx.x * 256;      // 0..767
    int t = c >> 8;
    int Nt = (t == 2) ? N2 : (t == 1 ? N1 : N0);
    float invn = 1.f / (float)Nt;
    float mean = bnsum[c] * invn;
    float var  = bnsq[c] * invn - mean * mean;
    float sc   = g[c] * rsqrtf(var + 1e-5f);
    scale[c] = sc;
    shift[c] = b[c] - mean * sc;
}

// bn + leaky-relu over all padded rows (h pad rows stay 0 -> deterministic)
__global__ void bn_apply_kernel(const float* __restrict__ in, float* __restrict__ outp,
                                __nv_bfloat16* __restrict__ oh, __nv_bfloat16* __restrict__ ol,
                                const float* __restrict__ scale, const float* __restrict__ shift,
                                int P1, int P2, int NPAD, int do_split) {
    int i = blockIdx.x * 256 + threadIdx.x;      // float4 over NPAD*256
    if (i >= NPAD * 64) return;
    int row = i >> 6;
    int t = (row >= P2) ? 2 : (row >= P1 ? 1 : 0);
    int c = t * 256 + (i & 63) * 4;
    float4 v  = *(const float4*)(in + (size_t)i * 4);
    float4 sc = *(const float4*)(scale + c);
    float4 sh = *(const float4*)(shift + c);
    float a0 = v.x * sc.x + sh.x;
    float a1 = v.y * sc.y + sh.y;
    float a2 = v.z * sc.z + sh.z;
    float a3 = v.w * sc.w + sh.w;
    float4 o;
    o.x = (a0 > 0.f) ? a0 : 0.01f * a0;
    o.y = (a1 > 0.f) ? a1 : 0.01f * a1;
    o.z = (a2 > 0.f) ? a2 : 0.01f * a2;
    o.w = (a3 > 0.f) ? a3 : 0.01f * a3;
    *(float4*)(outp + (size_t)i * 4) = o;
    if (do_split) {
        __nv_bfloat16 h0 = __float2bfloat16(o.x), h1 = __float2bfloat16(o.y);
        __nv_bfloat16 h2 = __float2bfloat16(o.z), h3 = __float2bfloat16(o.w);
        __nv_bfloat16 l0 = __float2bfloat16(o.x - __bfloat162float(h0));
        __nv_bfloat16 l1 = __float2bfloat16(o.y - __bfloat162float(h1));
        __nv_bfloat16 l2 = __float2bfloat16(o.z - __bfloat162float(h2));
        __nv_bfloat16 l3 = __float2bfloat16(o.w - __bfloat162float(h3));
        ((__nv_bfloat162*)oh)[2 * i]     = __halves2bfloat162(h0, h1);
        ((__nv_bfloat162*)oh)[2 * i + 1] = __halves2bfloat162(h2, h3);
        ((__nv_bfloat162*)ol)[2 * i]     = __halves2bfloat162(l0, l1);
        ((__nv_bfloat162*)ol)[2 * i + 1] = __halves2bfloat162(l2, l3);
    }
}

// ---------------- Classifier: warp per (compact) output row ----------------
__global__ __launch_bounds__(256) void classifier_kernel(
    const float* __restrict__ h, const float* __restrict__ cW,
    const float* __restrict__ cb, float* __restrict__ outp,
    int P1, int P2, int N0, int N1, int N2)
{
    int idx = (blockIdx.x * blockDim.x + threadIdx.x) >> 5;    // compact row
    int NT = N0 + N1 + N2;
    if (idx >= NT) return;
    int t  = (idx >= N0 + N1) ? 2 : (idx >= N0 ? 1 : 0);
    int Ct = (t == 2) ? N0 + N1 : (t == 1 ? N0 : 0);
    int Pt = (t == 2) ? P2 : (t == 1 ? P1 : 0);
    int row = Pt + (idx - Ct);
    int lane = threadIdx.x & 31;

    const float* hp = h + (size_t)row * 256 + lane * 8;
    float4 h0 = *(const float4*)hp;
    float4 h1 = *(const float4*)(hp + 4);
    float hv[8] = {h0.x, h0.y, h0.z, h0.w, h1.x, h1.y, h1.z, h1.w};

    const float* wp = cW + lane * 16;
    float4 w0 = *(const float4*)(wp + 0);
    float4 w1 = *(const float4*)(wp + 4);
    float4 w2 = *(const float4*)(wp + 8);
    float4 w3 = *(const float4*)(wp + 12);
    float wv[16] = {w0.x, w0.y, w0.z, w0.w, w1.x, w1.y, w1.z, w1.w,
                    w2.x, w2.y, w2.z, w2.w, w3.x, w3.y, w3.z, w3.w};

    float c0 = 0.f, c1 = 0.f;
#pragma unroll
    for (int j = 0; j < 8; j++) {
        c0 += hv[j] * wv[2 * j];
        c1 += hv[j] * wv[2 * j + 1];
    }
#pragma unroll
    for (int off = 16; off > 0; off >>= 1) {
        c0 += __shfl_xor_sync(0xffffffffu, c0, off);
        c1 += __shfl_xor_sync(0xffffffffu, c1, off);
    }
    if (lane == 0) {
        outp[(size_t)idx * 2 + 0] = c0 + cb[0];
        outp[(size_t)idx * 2 + 1] = c1 + cb[1];
    }
}

// ---------------- launch ----------------
extern "C" void kernel_launch(void* const* d_in, const int* in_sizes, int n_in,
                              void* d_out, int out_size) {
    const float* x[3];
    const int*   ei[3];
    for (int i = 0; i < 3; i++) {
        x[i]  = (const float*)d_in[i];
        ei[i] = (const int*)d_in[3 + i];
    }
    const float* Wl1  = (const float*)d_in[6];
    const float* Wr1  = (const float*)d_in[7];
    const float* att1 = (const float*)d_in[8];
    const float* b1   = (const float*)d_in[9];
    const float* Wl2  = (const float*)d_in[10];
    const float* Wr2  = (const float*)d_in[11];
    const float* att2 = (const float*)d_in[12];
    const float* b2   = (const float*)d_in[13];
    const float* bng  = (const float*)d_in[14];
    const float* bnb  = (const float*)d_in[15];
    const float* cW   = (const float*)d_in[16];
    const float* cb   = (const float*)d_in[17];
    float* out = (float*)d_out;

    float *hl, *hr, *h, *hn, *bnsum, *bnsq, *scale, *shift;
    __nv_bfloat16 *Ah, *Al, *Bh, *Bl;
    int *rowptr, *csrsrc, *deg, *cursor, *bsum;
    cudaGetSymbolAddress((void**)&hl,     g_hl);
    cudaGetSymbolAddress((void**)&hr,     g_hr);
    cudaGetSymbolAddress((void**)&h,      g_h);
    cudaGetSymbolAddress((void**)&hn,     g_hn);
    cudaGetSymbolAddress((void**)&Ah,     g_Ah);
    cudaGetSymbolAddress((void**)&Al,     g_Al);
    cudaGetSymbolAddress((void**)&Bh,     g_Bh);
    cudaGetSymbolAddress((void**)&Bl,     g_Bl);
    cudaGetSymbolAddress((void**)&rowptr, g_rowptr);
    cudaGetSymbolAddress((void**)&csrsrc, g_csrsrc);
    cudaGetSymbolAddress((void**)&deg,    g_deg);
    cudaGetSymbolAddress((void**)&cursor, g_cursor);
    cudaGetSymbolAddress((void**)&bsum,   g_bsum);
    cudaGetSymbolAddress((void**)&bnsum,  g_bnsum);
    cudaGetSymbolAddress((void**)&bnsq,   g_bnsq);
    cudaGetSymbolAddress((void**)&scale,  g_scale);
    cudaGetSymbolAddress((void**)&shift,  g_shift);

    cudaFuncSetAttribute(gemm_mma_kernel,
                         cudaFuncAttributeMaxDynamicSharedMemorySize, GEMM_SMEM);

    // geometry
    int N0 = in_sizes[0] / 128, N1 = in_sizes[1] / 128, N2 = in_sizes[2] / 128;
    int E0 = in_sizes[3] / 2,   E1 = in_sizes[4] / 2,   E2 = in_sizes[5] / 2;
    int T0 = (N0 + 127) / 128, T1 = (N1 + 127) / 128, T2 = (N2 + 127) / 128;
    int P1 = T0 * 128, P2 = P1 + T1 * 128;
    int NPAD = P2 + T2 * 128;
    int ET = E0 + E1 + E2;
    int ntile = NPAD / 128;

    // --- CSR build (once, shared by both layers) ---
    int nb = (NPAD + 1023) / 1024;
    cudaMemsetAsync(deg, 0, NPAD * sizeof(int), 0);
    hist_kernel<<<(ET + 255) / 256, 256>>>(ei[0] + E0, ei[1] + E1, ei[2] + E2,
                                           deg, E0, E1, E2, P1, P2);
    scan_bsum_kernel<<<nb, 256>>>(deg, bsum, NPAD);
    scan_boff_kernel<<<1, 32>>>(bsum, rowptr, nb, NPAD);
    scan_final_kernel<<<nb, 1024>>>(deg, bsum, rowptr, NPAD);
    cudaMemsetAsync(cursor, 0, NPAD * sizeof(int), 0);
    scatter_kernel<<<(ET + 255) / 256, 256>>>(ei[0], ei[0] + E0, ei[1], ei[1] + E1,
                                              ei[2], ei[2] + E2,
                                              rowptr, cursor, csrsrc, E0, E1, E2, P1, P2);

    // --- prep: split inputs + pack all weights ---
    split_x_kernel<<<(NPAD * 32 + 255) / 256, 256>>>(x[0], x[1], x[2], Ah, Al,
                                                     P1, P2, N0, N1, N2, NPAD);
    {
        int tot = 3 * 128 * 512 + 3 * 256 * 512;
        pack_weights_kernel<<<(tot + 255) / 256, 256>>>(Wl1, Wr1, Wl2, Wr2, Bh, Bl);
    }

    for (int layer = 0; layer < 2; layer++) {
        int K = (layer == 0) ? 128 : 256;
        int wbase = (layer == 0) ? 0 : L2_WOFF;
        const float* at = (layer == 0) ? att1 : att2;
        const float* bs = (layer == 0) ? b1 : b2;

        dim3 gg(4, ntile);
        gemm_mma_kernel<<<gg, 256, GEMM_SMEM>>>(Ah, Al, Bh, Bl, hl, hr,
                                                P1, P2, N0, N1, N2, K, wbase);

        gat_kernel<<<(NPAD * 32 + 255) / 256, 256>>>(hl, hr, rowptr, csrsrc, at, bs, h,
                                                     P1, P2, N0, N1, N2, NPAD);

        cudaMemsetAsync(bnsum, 0, 768 * sizeof(float), 0);
        cudaMemsetAsync(bnsq,  0, 768 * sizeof(float), 0);
        {
            dim3 gs(128, 3);
            bn_stats_kernel<<<gs, 256>>>(h, bnsum, bnsq, P1, P2, N0, N1, N2);
        }
        bn_final_kernel<<<3, 256>>>(bnsum, bnsq, bng, bnb, scale, shift, N0, N1, N2);
        bn_apply_kernel<<<(NPAD * 64 + 255) / 256, 256>>>(
            h, hn, Ah, Al, scale, shift, P1, P2, NPAD, layer == 0 ? 1 : 0);
    }

    classifier_kernel<<<((N0 + N1 + N2) * 32 + 255) / 256, 256>>>(
        hn, cW, cb, out, P1, P2, N0, N1, N2);
}

// round 13
// speedup vs baseline: 1.9329x; 1.0998x over previous
#include <cuda_runtime.h>
#include <cuda_fp16.h>
#include <math.h>
#include <stdint.h>

// ---------------- static scratch (no runtime allocation allowed) ----------------
#define MAXN 50000
#define NPADMAX (3 * 50048)          // per-type padded to 128 rows
#define MAXET (3 * 400000)

__device__ float g_hl[NPADMAX * 256];
__device__ float g_hr[NPADMAX * 256];
__device__ float g_h [NPADMAX * 256];
__device__ float g_hn[NPADMAX * 256];
__device__ __half g_Ah[NPADMAX * 256];
__device__ __half g_Al[NPADMAX * 256];
__device__ __half g_Bh[3 * (128 + 256) * 512];
__device__ int   g_rowptr[NPADMAX + 1];
__device__ int   g_csrsrc[MAXET];
__device__ int   g_deg[NPADMAX];
__device__ int   g_cursor[NPADMAX];
__device__ int   g_bsum[256];
__device__ float g_bnsum[768];
__device__ float g_bnsq[768];
__device__ float g_scale[768];
__device__ float g_shift[768];

#define L2_WOFF (3 * 128 * 512)      // offset of layer-2 weights inside g_Bh

// ---------------- baseline-PTX helpers (no 'a'-suffix features) ----------------
__device__ __forceinline__ uint32_t smem_u32(const void* p) {
    uint32_t a;
    asm("{ .reg .u64 t; cvta.to.shared.u64 t, %1; cvt.u32.u64 %0, t; }" : "=r"(a) : "l"(p));
    return a;
}
__device__ __forceinline__ void cp_async16(uint32_t dst, const void* src) {
    asm volatile("cp.async.cg.shared.global [%0], [%1], 16;" :: "r"(dst), "l"(src));
}
__device__ __forceinline__ void cp_commit() { asm volatile("cp.async.commit_group;" ::: "memory"); }
template <int N>
__device__ __forceinline__ void cp_wait() { asm volatile("cp.async.wait_group %0;" :: "n"(N) : "memory"); }

__device__ __forceinline__ void ldmat_x4(uint32_t addr, uint32_t& r0, uint32_t& r1,
                                         uint32_t& r2, uint32_t& r3) {
    asm volatile("ldmatrix.sync.aligned.m8n8.x4.shared.b16 {%0,%1,%2,%3}, [%4];"
                 : "=r"(r0), "=r"(r1), "=r"(r2), "=r"(r3) : "r"(addr));
}
__device__ __forceinline__ void ldmat_x4_t(uint32_t addr, uint32_t& r0, uint32_t& r1,
                                           uint32_t& r2, uint32_t& r3) {
    asm volatile("ldmatrix.sync.aligned.m8n8.x4.trans.shared.b16 {%0,%1,%2,%3}, [%4];"
                 : "=r"(r0), "=r"(r1), "=r"(r2), "=r"(r3) : "r"(addr));
}
__device__ __forceinline__ void mma_f16(float& c0, float& c1, float& c2, float& c3,
                                        uint32_t a0, uint32_t a1, uint32_t a2, uint32_t a3,
                                        uint32_t b0, uint32_t b1) {
    asm volatile("mma.sync.aligned.m16n8k16.row.col.f32.f16.f16.f32 "
                 "{%0,%1,%2,%3}, {%4,%5,%6,%7}, {%8,%9}, {%0,%1,%2,%3};"
                 : "+f"(c0), "+f"(c1), "+f"(c2), "+f"(c3)
                 : "r"(a0), "r"(a1), "r"(a2), "r"(a3), "r"(b0), "r"(b1));
}

// ---------------- HMMA GEMM: [hl|hr][M,256] = A[Mpad,K] @ Bcat_type[K,512] ----------------
// A = fp16 hi + fp16 residual (2-term, ~exact); B = single fp16.
// SMEM per stage: Ah[128][40]h @0, Al @10240, Bh[32][136]h @20480
#define KC 32
#define A_STR 40
#define B_STR 136
#define S_AH 0
#define S_AL 10240
#define S_BH 20480
#define STAGE_B 29184
#define GEMM_SMEM (2 * STAGE_B)

__global__ __launch_bounds__(256) void gemm_mma_kernel(
    const __half* __restrict__ Ah, const __half* __restrict__ Al,
    const __half* __restrict__ BhAll,
    float* __restrict__ Cl, float* __restrict__ Cr,
    int P1, int P2, int N0, int N1, int N2, int K, int wbase)
{
    extern __shared__ char smem[];
    const uint32_t sb = smem_u32(smem);
    const int tid  = threadIdx.x;
    const int lane = tid & 31;
    const int w    = tid >> 5;
    const int wm   = (w & 3) * 32;
    const int wn   = (w >> 2) * 64;
    const int bm   = blockIdx.y * 128;
    const int bn   = blockIdx.x * 128;   // within 512 concat cols

    const int t  = (bm >= P2) ? 2 : (bm >= P1 ? 1 : 0);
    const int Pt = (t == 2) ? P2 : (t == 1 ? P1 : 0);
    const int Nt = (t == 2) ? N2 : (t == 1 ? N1 : N0);
    const __half* __restrict__ Bh = BhAll + wbase + (size_t)t * K * 512;

    float* __restrict__ C = (bn < 256) ? Cl : Cr;
    const int cb0 = bn & 255;

    float acc[2][8][4];
#pragma unroll
    for (int i = 0; i < 2; i++)
#pragma unroll
        for (int j = 0; j < 8; j++)
#pragma unroll
            for (int k = 0; k < 4; k++) acc[i][j][k] = 0.f;

    const int nc = K >> 5;

    auto load_chunk = [&](int c) {
        const uint32_t st = sb + (c & 1) * STAGE_B;
        const int k0 = c * KC;
#pragma unroll
        for (int it = 0; it < 2; it++) {
            int lin = tid + it * 256;
            int row = lin >> 2, seg = lin & 3;
            const char* gA = (const char*)(Ah + (size_t)(bm + row) * K + k0 + seg * 8);
            const char* gL = (const char*)(Al + (size_t)(bm + row) * K + k0 + seg * 8);
            cp_async16(st + S_AH + row * (A_STR * 2) + seg * 16, gA);
            cp_async16(st + S_AL + row * (A_STR * 2) + seg * 16, gL);
        }
#pragma unroll
        for (int it = 0; it < 2; it++) {
            int lin = tid + it * 256;
            int row = lin >> 4, seg = lin & 15;
            const char* gH = (const char*)(Bh + (size_t)(k0 + row) * 512 + bn + seg * 8);
            cp_async16(st + S_BH + row * (B_STR * 2) + seg * 16, gH);
        }
    };

    load_chunk(0);
    cp_commit();

    for (int c = 0; c < nc; c++) {
        if (c + 1 < nc) { load_chunk(c + 1); cp_commit(); cp_wait<1>(); }
        else            { cp_wait<0>(); }
        __syncthreads();

        const uint32_t st = sb + (c & 1) * STAGE_B;
#pragma unroll
        for (int ks = 0; ks < 2; ks++) {
            const int kk = ks * 16;
            uint32_t ah[2][4], al[2][4];
#pragma unroll
            for (int mt = 0; mt < 2; mt++) {
                uint32_t off = ((wm + mt * 16 + (lane & 15)) * A_STR + kk + (lane >> 4) * 8) * 2;
                ldmat_x4(st + S_AH + off, ah[mt][0], ah[mt][1], ah[mt][2], ah[mt][3]);
                ldmat_x4(st + S_AL + off, al[mt][0], al[mt][1], al[mt][2], al[mt][3]);
            }
            uint32_t bh[4][4];
#pragma unroll
            for (int np = 0; np < 4; np++) {
                uint32_t off = ((kk + (lane & 15)) * B_STR + wn + np * 16 + (lane >> 4) * 8) * 2;
                ldmat_x4_t(st + S_BH + off, bh[np][0], bh[np][1], bh[np][2], bh[np][3]);
            }
#pragma unroll
            for (int mt = 0; mt < 2; mt++)
#pragma unroll
                for (int np = 0; np < 4; np++)
#pragma unroll
                    for (int half = 0; half < 2; half++) {
                        int nt = np * 2 + half;
                        float* a = acc[mt][nt];
                        uint32_t b0 = bh[np][half * 2], b1 = bh[np][half * 2 + 1];
                        mma_f16(a[0], a[1], a[2], a[3],
                                ah[mt][0], ah[mt][1], ah[mt][2], ah[mt][3], b0, b1);
                        mma_f16(a[0], a[1], a[2], a[3],
                                al[mt][0], al[mt][1], al[mt][2], al[mt][3], b0, b1);
                    }
        }
        __syncthreads();
    }

    const int g4 = lane >> 2, t4 = lane & 3;
#pragma unroll
    for (int mt = 0; mt < 2; mt++) {
        int r0 = bm + wm + mt * 16 + g4;
        int r1 = r0 + 8;
#pragma unroll
        for (int nt = 0; nt < 8; nt++) {
            int col = cb0 + wn + nt * 8 + t4 * 2;
            if (r0 - Pt < Nt) *(float2*)(C + (size_t)r0 * 256 + col) =
                make_float2(acc[mt][nt][0], acc[mt][nt][1]);
            if (r1 - Pt < Nt) *(float2*)(C + (size_t)r1 * 256 + col) =
                make_float2(acc[mt][nt][2], acc[mt][nt][3]);
        }
    }
}

// ---------------- layer-1 split: x (3 ptrs) -> Ah/Al [NPAD,128] fp16 hi/residual ----------------
__global__ void split_x_kernel(const float* __restrict__ x0, const float* __restrict__ x1,
                               const float* __restrict__ x2,
                               __half* __restrict__ hi, __half* __restrict__ lo,
                               int P1, int P2, int N0, int N1, int N2, int NPAD) {
    int i = blockIdx.x * 256 + threadIdx.x;      // float4 index over NPAD*128
    if (i >= NPAD * 32) return;
    int row = i >> 5, q = i & 31;
    int t  = (row >= P2) ? 2 : (row >= P1 ? 1 : 0);
    int Pt = (t == 2) ? P2 : (t == 1 ? P1 : 0);
    int Nt = (t == 2) ? N2 : (t == 1 ? N1 : N0);
    const float* xp = (t == 2) ? x2 : (t == 1 ? x1 : x0);
    int lr = row - Pt;
    float4 v = make_float4(0.f, 0.f, 0.f, 0.f);
    if (lr < Nt) v = ((const float4*)xp)[lr * 32 + q];
    __half h0 = __float2half(v.x), h1 = __float2half(v.y);
    __half h2 = __float2half(v.z), h3 = __float2half(v.w);
    __half l0 = __float2half(v.x - __half2float(h0));
    __half l1 = __float2half(v.y - __half2float(h1));
    __half l2 = __float2half(v.z - __half2float(h2));
    __half l3 = __float2half(v.w - __half2float(h3));
    ((__half2*)hi)[2 * i]     = __halves2half2(h0, h1);
    ((__half2*)hi)[2 * i + 1] = __halves2half2(h2, h3);
    ((__half2*)lo)[2 * i]     = __halves2half2(l0, l1);
    ((__half2*)lo)[2 * i + 1] = __halves2half2(l2, l3);
}

// ---------------- pack ALL weights (both layers, 3 types) -> Bcat fp16 ----------------
__global__ void pack_weights_kernel(const float* __restrict__ Wl1, const float* __restrict__ Wr1,
                                    const float* __restrict__ Wl2, const float* __restrict__ Wr2,
                                    __half* __restrict__ th) {
    int idx = blockIdx.x * 256 + threadIdx.x;
    const int L1 = 3 * 128 * 512;
    const int TOT = L1 + 3 * 256 * 512;
    if (idx >= TOT) return;
    float v;
    if (idx < L1) {
        int t = idx / (128 * 512), rem = idx % (128 * 512);
        int k = rem >> 9, c = rem & 511;
        v = (c < 256) ? Wl1[(size_t)t * 128 * 256 + k * 256 + c]
                      : Wr1[(size_t)t * 128 * 256 + k * 256 + (c - 256)];
    } else {
        int j = idx - L1;
        int t = j / (256 * 512), rem = j % (256 * 512);
        int k = rem >> 9, c = rem & 511;
        v = (c < 256) ? Wl2[(size_t)t * 256 * 256 + k * 256 + c]
                      : Wr2[(size_t)t * 256 * 256 + k * 256 + (c - 256)];
    }
    th[idx] = __float2half(v);
}

// ---------------- CSR build (all types, global padded node ids) ----------------
__global__ void hist_kernel(const int* __restrict__ d0, const int* __restrict__ d1,
                            const int* __restrict__ d2, int* __restrict__ deg,
                            int E0, int E1, int E2, int P1, int P2) {
    int e = blockIdx.x * 256 + threadIdx.x;
    int dv;
    if (e < E0) dv = d0[e];
    else if (e < E0 + E1) dv = d1[e - E0] + P1;
    else if (e < E0 + E1 + E2) dv = d2[e - E0 - E1] + P2;
    else return;
    atomicAdd(&deg[dv], 1);
}

__global__ void scan_bsum_kernel(const int* __restrict__ deg, int* __restrict__ bsum, int N) {
    __shared__ int sh[256];
    int b = blockIdx.x, t = threadIdx.x;
    int s = 0;
    for (int j = t; j < 1024; j += 256) {
        int i = b * 1024 + j;
        if (i < N) s += deg[i];
    }
    sh[t] = s;
    __syncthreads();
    for (int off = 128; off > 0; off >>= 1) {
        if (t < off) sh[t] += sh[t + off];
        __syncthreads();
    }
    if (t == 0) bsum[b] = sh[0];
}

__global__ void scan_boff_kernel(int* __restrict__ bsum, int* __restrict__ rowptr,
                                 int nb, int N) {
    if (threadIdx.x == 0) {
        int acc = 0;
        for (int b = 0; b < nb; b++) { int v = bsum[b]; bsum[b] = acc; acc += v; }
        rowptr[N] = acc;
    }
}

__global__ void scan_final_kernel(const int* __restrict__ deg, const int* __restrict__ bsum,
                                  int* __restrict__ rowptr, int N) {
    __shared__ int sh[1024];
    int b = blockIdx.x, t = threadIdx.x;
    int i = b * 1024 + t;
    int v = (i < N) ? deg[i] : 0;
    sh[t] = v;
    __syncthreads();
    for (int off = 1; off < 1024; off <<= 1) {
        int u = (t >= off) ? sh[t - off] : 0;
        __syncthreads();
        sh[t] += u;
        __syncthreads();
    }
    if (i < N) rowptr[i] = bsum[b] + sh[t] - v;
}

__global__ void scatter_kernel(const int* __restrict__ s0, const int* __restrict__ d0,
                               const int* __restrict__ s1, const int* __restrict__ d1,
                               const int* __restrict__ s2, const int* __restrict__ d2,
                               const int* __restrict__ rowptr, int* __restrict__ cursor,
                               int* __restrict__ csrsrc,
                               int E0, int E1, int E2, int P1, int P2) {
    int e = blockIdx.x * 256 + threadIdx.x;
    int sv, dv;
    if (e < E0)                { sv = s0[e];            dv = d0[e]; }
    else if (e < E0 + E1)      { sv = s1[e - E0] + P1;  dv = d1[e - E0] + P1; }
    else if (e < E0 + E1 + E2) { sv = s2[e - E0 - E1] + P2; dv = d2[e - E0 - E1] + P2; }
    else return;
    int pos = atomicAdd(&cursor[dv], 1);
    csrsrc[rowptr[dv] + pos] = sv;
}

// ---------------- GATv2 aggregate (all types): one warp per dst node ----------------
__global__ __launch_bounds__(256) void gat_kernel(
    const float* __restrict__ hl, const float* __restrict__ hr,
    const int* __restrict__ rowptr, const int* __restrict__ csrsrc,
    const float* __restrict__ attAll, const float* __restrict__ biasAll,
    float* __restrict__ out, int P1, int P2, int N0, int N1, int N2, int NPAD)
{
    int d = (blockIdx.x * blockDim.x + threadIdx.x) >> 5;
    if (d >= NPAD) return;
    int t  = (d >= P2) ? 2 : (d >= P1 ? 1 : 0);
    int Pt = (t == 2) ? P2 : (t == 1 ? P1 : 0);
    int Nt = (t == 2) ? N2 : (t == 1 ? N1 : N0);
    if (d - Pt >= Nt) return;                     // pad node
    int lane = threadIdx.x & 31;
    int base = lane * 8;
    const float* att  = attAll + t * 256;
    const float* bias = biasAll + t * 256;

    float4 at0 = *(const float4*)(att + base);
    float4 at1 = *(const float4*)(att + base + 4);
    float atv[8] = {at0.x, at0.y, at0.z, at0.w, at1.x, at1.y, at1.z, at1.w};

    const float* hrp = hr + (size_t)d * 256 + base;
    float4 r0 = *(const float4*)hrp;
    float4 r1 = *(const float4*)(hrp + 4);
    float hrv[8] = {r0.x, r0.y, r0.z, r0.w, r1.x, r1.y, r1.z, r1.w};

    float m = -1.0e30f, den = 0.f;
    float acc[8] = {0.f, 0.f, 0.f, 0.f, 0.f, 0.f, 0.f, 0.f};

    int e0 = rowptr[d], e1 = rowptr[d + 1];
    for (int e = e0 - 1; e < e1; e++) {          // e == e0-1 -> self loop
        int s = (e < e0) ? d : csrsrc[e];
        const float* hp = hl + (size_t)s * 256 + base;
        float4 h0 = *(const float4*)hp;
        float4 h1 = *(const float4*)(hp + 4);
        float hv[8] = {h0.x, h0.y, h0.z, h0.w, h1.x, h1.y, h1.z, h1.w};

        float p = 0.f;
#pragma unroll
        for (int j = 0; j < 8; j++) {
            float v = hv[j] + hrv[j];
            v = (v > 0.f) ? v : 0.2f * v;
            p += v * atv[j];
        }
        p += __shfl_xor_sync(0xffffffffu, p, 1);
        p += __shfl_xor_sync(0xffffffffu, p, 2);
        p += __shfl_xor_sync(0xffffffffu, p, 4);

        float nm = fmaxf(m, p);
        float f  = __expf(m - nm);
        float wv = __expf(p - nm);
        den = den * f + wv;
        m = nm;
#pragma unroll
        for (int j = 0; j < 8; j++) acc[j] = acc[j] * f + wv * hv[j];
    }

    float inv = 1.f / (den + 1e-16f);
    float* op = out + (size_t)d * 256 + base;
    float4 o0, o1;
    o0.x = acc[0] * inv + bias[base + 0];
    o0.y = acc[1] * inv + bias[base + 1];
    o0.z = acc[2] * inv + bias[base + 2];
    o0.w = acc[3] * inv + bias[base + 3];
    o1.x = acc[4] * inv + bias[base + 4];
    o1.y = acc[5] * inv + bias[base + 5];
    o1.z = acc[6] * inv + bias[base + 6];
    o1.w = acc[7] * inv + bias[base + 7];
    *(float4*)op       = o0;
    *(float4*)(op + 4) = o1;
}

// ---------------- BatchNorm (per-type stats, grid.y = type) ----------------
__global__ void bn_stats_kernel(const float* __restrict__ x,
                                float* __restrict__ bnsum, float* __restrict__ bnsq,
                                int P1, int P2, int N0, int N1, int N2) {
    int t = blockIdx.y;
    int Pt = (t == 2) ? P2 : (t == 1 ? P1 : 0);
    int Nt = (t == 2) ? N2 : (t == 1 ? N1 : N0);
    int c = threadIdx.x;
    float s = 0.f, q = 0.f;
    for (int r = blockIdx.x; r < Nt; r += gridDim.x) {
        float v = x[(size_t)(Pt + r) * 256 + c];
        s += v;
        q += v * v;
    }
    atomicAdd(&bnsum[t * 256 + c], s);
    atomicAdd(&bnsq[t * 256 + c], q);
}

__global__ void bn_final_kernel(const float* __restrict__ bnsum, const float* __restrict__ bnsq,
                                const float* __restrict__ g, const float* __restrict__ b,
                                float* __restrict__ scale, float* __restrict__ shift,
                                int N0, int N1, int N2) {
    int c = threadIdx.x + blockIdx.x * 256;      // 0..767
    int t = c >> 8;
    int Nt = (t == 2) ? N2 : (t == 1 ? N1 : N0);
    float invn = 1.f / (float)Nt;
    float mean = bnsum[c] * invn;
    float var  = bnsq[c] * invn - mean * mean;
    float sc   = g[c] * rsqrtf(var + 1e-5f);
    scale[c] = sc;
    shift[c] = b[c] - mean * sc;
}

// bn + leaky-relu over all padded rows; optional fp16 hi/lo emit for next GEMM
__global__ void bn_apply_kernel(const float* __restrict__ in, float* __restrict__ outp,
                                __half* __restrict__ oh, __half* __restrict__ ol,
                                const float* __restrict__ scale, const float* __restrict__ shift,
                                int P1, int P2, int NPAD, int do_split) {
    int i = blockIdx.x * 256 + threadIdx.x;      // float4 over NPAD*256
    if (i >= NPAD * 64) return;
    int row = i >> 6;
    int t = (row >= P2) ? 2 : (row >= P1 ? 1 : 0);
    int c = t * 256 + (i & 63) * 4;
    float4 v  = *(const float4*)(in + (size_t)i * 4);
    float4 sc = *(const float4*)(scale + c);
    float4 sh = *(const float4*)(shift + c);
    float a0 = v.x * sc.x + sh.x;
    float a1 = v.y * sc.y + sh.y;
    float a2 = v.z * sc.z + sh.z;
    float a3 = v.w * sc.w + sh.w;
    float4 o;
    o.x = (a0 > 0.f) ? a0 : 0.01f * a0;
    o.y = (a1 > 0.f) ? a1 : 0.01f * a1;
    o.z = (a2 > 0.f) ? a2 : 0.01f * a2;
    o.w = (a3 > 0.f) ? a3 : 0.01f * a3;
    *(float4*)(outp + (size_t)i * 4) = o;
    if (do_split) {
        __half h0 = __float2half(o.x), h1 = __float2half(o.y);
        __half h2 = __float2half(o.z), h3 = __float2half(o.w);
        __half l0 = __float2half(o.x - __half2float(h0));
        __half l1 = __float2half(o.y - __half2float(h1));
        __half l2 = __float2half(o.z - __half2float(h2));
        __half l3 = __float2half(o.w - __half2float(h3));
        ((__half2*)oh)[2 * i]     = __halves2half2(h0, h1);
        ((__half2*)oh)[2 * i + 1] = __halves2half2(h2, h3);
        ((__half2*)ol)[2 * i]     = __halves2half2(l0, l1);
        ((__half2*)ol)[2 * i + 1] = __halves2half2(l2, l3);
    }
}

// ---------------- Classifier: warp per (compact) output row ----------------
__global__ __launch_bounds__(256) void classifier_kernel(
    const float* __restrict__ h, const float* __restrict__ cW,
    const float* __restrict__ cb, float* __restrict__ outp,
    int P1, int P2, int N0, int N1, int N2)
{
    int idx = (blockIdx.x * blockDim.x + threadIdx.x) >> 5;    // compact row
    int NT = N0 + N1 + N2;
    if (idx >= NT) return;
    int t  = (idx >= N0 + N1) ? 2 : (idx >= N0 ? 1 : 0);
    int Ct = (t == 2) ? N0 + N1 : (t == 1 ? N0 : 0);
    int Pt = (t == 2) ? P2 : (t == 1 ? P1 : 0);
    int row = Pt + (idx - Ct);
    int lane = threadIdx.x & 31;

    const float* hp = h + (size_t)row * 256 + lane * 8;
    float4 h0 = *(const float4*)hp;
    float4 h1 = *(const float4*)(hp + 4);
    float hv[8] = {h0.x, h0.y, h0.z, h0.w, h1.x, h1.y, h1.z, h1.w};

    const float* wp = cW + lane * 16;
    float4 w0 = *(const float4*)(wp + 0);
    float4 w1 = *(const float4*)(wp + 4);
    float4 w2 = *(const float4*)(wp + 8);
    float4 w3 = *(const float4*)(wp + 12);
    float wv[16] = {w0.x, w0.y, w0.z, w0.w, w1.x, w1.y, w1.z, w1.w,
                    w2.x, w2.y, w2.z, w2.w, w3.x, w3.y, w3.z, w3.w};

    float c0 = 0.f, c1 = 0.f;
#pragma unroll
    for (int j = 0; j < 8; j++) {
        c0 += hv[j] * wv[2 * j];
        c1 += hv[j] * wv[2 * j + 1];
    }
#pragma unroll
    for (int off = 16; off > 0; off >>= 1) {
        c0 += __shfl_xor_sync(0xffffffffu, c0, off);
        c1 += __shfl_xor_sync(0xffffffffu, c1, off);
    }
    if (lane == 0) {
        outp[(size_t)idx * 2 + 0] = c0 + cb[0];
        outp[(size_t)idx * 2 + 1] = c1 + cb[1];
    }
}

// ---------------- launch ----------------
extern "C" void kernel_launch(void* const* d_in, const int* in_sizes, int n_in,
                              void* d_out, int out_size) {
    const float* x[3];
    const int*   ei[3];
    for (int i = 0; i < 3; i++) {
        x[i]  = (const float*)d_in[i];
        ei[i] = (const int*)d_in[3 + i];
    }
    const float* Wl1  = (const float*)d_in[6];
    const float* Wr1  = (const float*)d_in[7];
    const float* att1 = (const float*)d_in[8];
    const float* b1   = (const float*)d_in[9];
    const float* Wl2  = (const float*)d_in[10];
    const float* Wr2  = (const float*)d_in[11];
    const float* att2 = (const float*)d_in[12];
    const float* b2   = (const float*)d_in[13];
    const float* bng  = (const float*)d_in[14];
    const float* bnb  = (const float*)d_in[15];
    const float* cW   = (const float*)d_in[16];
    const float* cb   = (const float*)d_in[17];
    float* out = (float*)d_out;

    float *hl, *hr, *h, *hn, *bnsum, *bnsq, *scale, *shift;
    __half *Ah, *Al, *Bh;
    int *rowptr, *csrsrc, *deg, *cursor, *bsum;
    cudaGetSymbolAddress((void**)&hl,     g_hl);
    cudaGetSymbolAddress((void**)&hr,     g_hr);
    cudaGetSymbolAddress((void**)&h,      g_h);
    cudaGetSymbolAddress((void**)&hn,     g_hn);
    cudaGetSymbolAddress((void**)&Ah,     g_Ah);
    cudaGetSymbolAddress((void**)&Al,     g_Al);
    cudaGetSymbolAddress((void**)&Bh,     g_Bh);
    cudaGetSymbolAddress((void**)&rowptr, g_rowptr);
    cudaGetSymbolAddress((void**)&csrsrc, g_csrsrc);
    cudaGetSymbolAddress((void**)&deg,    g_deg);
    cudaGetSymbolAddress((void**)&cursor, g_cursor);
    cudaGetSymbolAddress((void**)&bsum,   g_bsum);
    cudaGetSymbolAddress((void**)&bnsum,  g_bnsum);
    cudaGetSymbolAddress((void**)&bnsq,   g_bnsq);
    cudaGetSymbolAddress((void**)&scale,  g_scale);
    cudaGetSymbolAddress((void**)&shift,  g_shift);

    cudaFuncSetAttribute(gemm_mma_kernel,
                         cudaFuncAttributeMaxDynamicSharedMemorySize, GEMM_SMEM);

    // geometry
    int N0 = in_sizes[0] / 128, N1 = in_sizes[1] / 128, N2 = in_sizes[2] / 128;
    int E0 = in_sizes[3] / 2,   E1 = in_sizes[4] / 2,   E2 = in_sizes[5] / 2;
    int T0 = (N0 + 127) / 128, T1 = (N1 + 127) / 128, T2 = (N2 + 127) / 128;
    int P1 = T0 * 128, P2 = P1 + T1 * 128;
    int NPAD = P2 + T2 * 128;
    int ET = E0 + E1 + E2;
    int ntile = NPAD / 128;
    int nb = (NPAD + 1023) / 1024;

    // --- prep (launch order puts layer-1 GEMM at ncu skip index 5) ---
    split_x_kernel<<<(NPAD * 32 + 255) / 256, 256>>>(x[0], x[1], x[2], Ah, Al,
                                                     P1, P2, N0, N1, N2, NPAD);   // 0
    {
        int tot = 3 * 128 * 512 + 3 * 256 * 512;
        pack_weights_kernel<<<(tot + 255) / 256, 256>>>(Wl1, Wr1, Wl2, Wr2, Bh);  // 1
    }
    cudaMemsetAsync(deg, 0, NPAD * sizeof(int), 0);                               // 2
    hist_kernel<<<(ET + 255) / 256, 256>>>(ei[0] + E0, ei[1] + E1, ei[2] + E2,
                                           deg, E0, E1, E2, P1, P2);              // 3
    scan_bsum_kernel<<<nb, 256>>>(deg, bsum, NPAD);                               // 4

    dim3 gg(4, ntile);
    gemm_mma_kernel<<<gg, 256, GEMM_SMEM>>>(Ah, Al, Bh, hl, hr,
                                            P1, P2, N0, N1, N2, 128, 0);          // 5 (profiled)

    scan_boff_kernel<<<1, 32>>>(bsum, rowptr, nb, NPAD);
    scan_final_kernel<<<nb, 1024>>>(deg, bsum, rowptr, NPAD);
    cudaMemsetAsync(cursor, 0, NPAD * sizeof(int), 0);
    scatter_kernel<<<(ET + 255) / 256, 256>>>(ei[0], ei[0] + E0, ei[1], ei[1] + E1,
                                              ei[2], ei[2] + E2,
                                              rowptr, cursor, csrsrc, E0, E1, E2, P1, P2);

    for (int layer = 0; layer < 2; layer++) {
        if (layer == 1) {
            gemm_mma_kernel<<<gg, 256, GEMM_SMEM>>>(Ah, Al, Bh, hl, hr,
                                                    P1, P2, N0, N1, N2, 256, L2_WOFF);
        }
        const float* at = (layer == 0) ? att1 : att2;
        const float* bs = (layer == 0) ? b1 : b2;

        gat_kernel<<<(NPAD * 32 + 255) / 256, 256>>>(hl, hr, rowptr, csrsrc, at, bs, h,
                                                     P1, P2, N0, N1, N2, NPAD);

        cudaMemsetAsync(bnsum, 0, 768 * sizeof(float), 0);
        cudaMemsetAsync(bnsq,  0, 768 * sizeof(float), 0);
        {
            dim3 gs(128, 3);
            bn_stats_kernel<<<gs, 256>>>(h, bnsum, bnsq, P1, P2, N0, N1, N2);
        }
        bn_final_kernel<<<3, 256>>>(bnsum, bnsq, bng, bnb, scale, shift, N0, N1, N2);
        bn_apply_kernel<<<(NPAD * 64 + 255) / 256, 256>>>(
            h, hn, Ah, Al, scale, shift, P1, P2, NPAD, layer == 0 ? 1 : 0);
    }

    classifier_kernel<<<((N0 + N1 + N2) * 32 + 255) / 256, 256>>>(
        hn, cW, cb, out, P1, P2, N0, N1, N2);
}

// round 15
// speedup vs baseline: 1.9479x; 1.0077x over previous
#include <cuda_runtime.h>
#include <cuda_fp16.h>
#include <math.h>
#include <stdint.h>

// ---------------- static scratch (no runtime allocation allowed) ----------------
#define MAXN 50000
#define NPADMAX (3 * 50048)          // per-type padded to 128 rows
#define MAXET (3 * 400000)

__device__ float g_hl[NPADMAX * 256];
__device__ float g_hr[NPADMAX * 256];
__device__ float g_h [NPADMAX * 256];
__device__ float g_hn[NPADMAX * 256];
__device__ __half g_Ah[NPADMAX * 256];
__device__ __half g_Al[NPADMAX * 256];
__device__ __half g_Bh[3 * (128 + 256) * 512];
__device__ int   g_rowptr[NPADMAX + 1];
__device__ int   g_csrsrc[MAXET];
__device__ int   g_deg[NPADMAX];
__device__ int   g_cursor[NPADMAX];
__device__ int   g_bsum[256];
__device__ float g_bnsum[768];
__device__ float g_bnsq[768];
__device__ float g_scale[768];
__device__ float g_shift[768];

#define L2_WOFF (3 * 128 * 512)      // offset of layer-2 weights inside g_Bh

// ---------------- baseline-PTX helpers (no 'a'-suffix features) ----------------
__device__ __forceinline__ uint32_t smem_u32(const void* p) {
    uint32_t a;
    asm("{ .reg .u64 t; cvta.to.shared.u64 t, %1; cvt.u32.u64 %0, t; }" : "=r"(a) : "l"(p));
    return a;
}
__device__ __forceinline__ void cp_async16(uint32_t dst, const void* src) {
    asm volatile("cp.async.cg.shared.global [%0], [%1], 16;" :: "r"(dst), "l"(src));
}
__device__ __forceinline__ void cp_commit() { asm volatile("cp.async.commit_group;" ::: "memory"); }
template <int N>
__device__ __forceinline__ void cp_wait() { asm volatile("cp.async.wait_group %0;" :: "n"(N) : "memory"); }

__device__ __forceinline__ void ldmat_x4(uint32_t addr, uint32_t& r0, uint32_t& r1,
                                         uint32_t& r2, uint32_t& r3) {
    asm volatile("ldmatrix.sync.aligned.m8n8.x4.shared.b16 {%0,%1,%2,%3}, [%4];"
                 : "=r"(r0), "=r"(r1), "=r"(r2), "=r"(r3) : "r"(addr));
}
__device__ __forceinline__ void ldmat_x4_t(uint32_t addr, uint32_t& r0, uint32_t& r1,
                                           uint32_t& r2, uint32_t& r3) {
    asm volatile("ldmatrix.sync.aligned.m8n8.x4.trans.shared.b16 {%0,%1,%2,%3}, [%4];"
                 : "=r"(r0), "=r"(r1), "=r"(r2), "=r"(r3) : "r"(addr));
}
__device__ __forceinline__ void mma_f16(float& c0, float& c1, float& c2, float& c3,
                                        uint32_t a0, uint32_t a1, uint32_t a2, uint32_t a3,
                                        uint32_t b0, uint32_t b1) {
    asm volatile("mma.sync.aligned.m16n8k16.row.col.f32.f16.f16.f32 "
                 "{%0,%1,%2,%3}, {%4,%5,%6,%7}, {%8,%9}, {%0,%1,%2,%3};"
                 : "+f"(c0), "+f"(c1), "+f"(c2), "+f"(c3)
                 : "r"(a0), "r"(a1), "r"(a2), "r"(a3), "r"(b0), "r"(b1));
}

// ---------------- HMMA GEMM: [hl|hr][M,256] = A[Mpad,K] @ Bcat_type[K,512] ----------------
// A = fp16 hi + fp16 residual (2-term, ~exact); B = single fp16.
// SMEM per stage: Ah[128][40]h @0, Al @10240, Bh[32][136]h @20480
#define KC 32
#define A_STR 40
#define B_STR 136
#define S_AH 0
#define S_AL 10240
#define S_BH 20480
#define STAGE_B 29184
#define GEMM_SMEM (2 * STAGE_B)

__global__ __launch_bounds__(256) void gemm_mma_kernel(
    const __half* __restrict__ Ah, const __half* __restrict__ Al,
    const __half* __restrict__ BhAll,
    float* __restrict__ Cl, float* __restrict__ Cr,
    int P1, int P2, int N0, int N1, int N2, int K, int wbase)
{
    extern __shared__ char smem[];
    const uint32_t sb = smem_u32(smem);
    const int tid  = threadIdx.x;
    const int lane = tid & 31;
    const int w    = tid >> 5;
    const int wm   = (w & 3) * 32;
    const int wn   = (w >> 2) * 64;
    const int bm   = blockIdx.y * 128;
    const int bn   = blockIdx.x * 128;   // within 512 concat cols

    const int t  = (bm >= P2) ? 2 : (bm >= P1 ? 1 : 0);
    const int Pt = (t == 2) ? P2 : (t == 1 ? P1 : 0);
    const int Nt = (t == 2) ? N2 : (t == 1 ? N1 : N0);
    const __half* __restrict__ Bh = BhAll + wbase + (size_t)t * K * 512;

    float* __restrict__ C = (bn < 256) ? Cl : Cr;
    const int cb0 = bn & 255;

    float acc[2][8][4];
#pragma unroll
    for (int i = 0; i < 2; i++)
#pragma unroll
        for (int j = 0; j < 8; j++)
#pragma unroll
            for (int k = 0; k < 4; k++) acc[i][j][k] = 0.f;

    const int nc = K >> 5;

    auto load_chunk = [&](int c) {
        const uint32_t st = sb + (c & 1) * STAGE_B;
        const int k0 = c * KC;
#pragma unroll
        for (int it = 0; it < 2; it++) {
            int lin = tid + it * 256;
            int row = lin >> 2, seg = lin & 3;
            const char* gA = (const char*)(Ah + (size_t)(bm + row) * K + k0 + seg * 8);
            const char* gL = (const char*)(Al + (size_t)(bm + row) * K + k0 + seg * 8);
            cp_async16(st + S_AH + row * (A_STR * 2) + seg * 16, gA);
            cp_async16(st + S_AL + row * (A_STR * 2) + seg * 16, gL);
        }
#pragma unroll
        for (int it = 0; it < 2; it++) {
            int lin = tid + it * 256;
            int row = lin >> 4, seg = lin & 15;
            const char* gH = (const char*)(Bh + (size_t)(k0 + row) * 512 + bn + seg * 8);
            cp_async16(st + S_BH + row * (B_STR * 2) + seg * 16, gH);
        }
    };

    load_chunk(0);
    cp_commit();

    for (int c = 0; c < nc; c++) {
        if (c + 1 < nc) { load_chunk(c + 1); cp_commit(); cp_wait<1>(); }
        else            { cp_wait<0>(); }
        __syncthreads();

        const uint32_t st = sb + (c & 1) * STAGE_B;
#pragma unroll
        for (int ks = 0; ks < 2; ks++) {
            const int kk = ks * 16;
            uint32_t ah[2][4], al[2][4];
#pragma unroll
            for (int mt = 0; mt < 2; mt++) {
                uint32_t off = ((wm + mt * 16 + (lane & 15)) * A_STR + kk + (lane >> 4) * 8) * 2;
                ldmat_x4(st + S_AH + off, ah[mt][0], ah[mt][1], ah[mt][2], ah[mt][3]);
                ldmat_x4(st + S_AL + off, al[mt][0], al[mt][1], al[mt][2], al[mt][3]);
            }
            uint32_t bh[4][4];
#pragma unroll
            for (int np = 0; np < 4; np++) {
                uint32_t off = ((kk + (lane & 15)) * B_STR + wn + np * 16 + (lane >> 4) * 8) * 2;
                ldmat_x4_t(st + S_BH + off, bh[np][0], bh[np][1], bh[np][2], bh[np][3]);
            }
#pragma unroll
            for (int mt = 0; mt < 2; mt++)
#pragma unroll
                for (int np = 0; np < 4; np++)
#pragma unroll
                    for (int half = 0; half < 2; half++) {
                        int nt = np * 2 + half;
                        float* a = acc[mt][nt];
                        uint32_t b0 = bh[np][half * 2], b1 = bh[np][half * 2 + 1];
                        mma_f16(a[0], a[1], a[2], a[3],
                                ah[mt][0], ah[mt][1], ah[mt][2], ah[mt][3], b0, b1);
                        mma_f16(a[0], a[1], a[2], a[3],
                                al[mt][0], al[mt][1], al[mt][2], al[mt][3], b0, b1);
                    }
        }
        __syncthreads();
    }

    const int g4 = lane >> 2, t4 = lane & 3;
#pragma unroll
    for (int mt = 0; mt < 2; mt++) {
        int r0 = bm + wm + mt * 16 + g4;
        int r1 = r0 + 8;
#pragma unroll
        for (int nt = 0; nt < 8; nt++) {
            int col = cb0 + wn + nt * 8 + t4 * 2;
            if (r0 - Pt < Nt) *(float2*)(C + (size_t)r0 * 256 + col) =
                make_float2(acc[mt][nt][0], acc[mt][nt][1]);
            if (r1 - Pt < Nt) *(float2*)(C + (size_t)r1 * 256 + col) =
                make_float2(acc[mt][nt][2], acc[mt][nt][3]);
        }
    }
}

// ---------------- layer-1 split: x (3 ptrs) -> Ah/Al [NPAD,128] fp16 hi/residual ----------------
__global__ void split_x_kernel(const float* __restrict__ x0, const float* __restrict__ x1,
                               const float* __restrict__ x2,
                               __half* __restrict__ hi, __half* __restrict__ lo,
                               int P1, int P2, int N0, int N1, int N2, int NPAD) {
    int i = blockIdx.x * 256 + threadIdx.x;      // float4 index over NPAD*128
    if (i >= NPAD * 32) return;
    int row = i >> 5, q = i & 31;
    int t  = (row >= P2) ? 2 : (row >= P1 ? 1 : 0);
    int Pt = (t == 2) ? P2 : (t == 1 ? P1 : 0);
    int Nt = (t == 2) ? N2 : (t == 1 ? N1 : N0);
    const float* xp = (t == 2) ? x2 : (t == 1 ? x1 : x0);
    int lr = row - Pt;
    float4 v = make_float4(0.f, 0.f, 0.f, 0.f);
    if (lr < Nt) v = ((const float4*)xp)[lr * 32 + q];
    __half h0 = __float2half(v.x), h1 = __float2half(v.y);
    __half h2 = __float2half(v.z), h3 = __float2half(v.w);
    __half l0 = __float2half(v.x - __half2float(h0));
    __half l1 = __float2half(v.y - __half2float(h1));
    __half l2 = __float2half(v.z - __half2float(h2));
    __half l3 = __float2half(v.w - __half2float(h3));
    ((__half2*)hi)[2 * i]     = __halves2half2(h0, h1);
    ((__half2*)hi)[2 * i + 1] = __halves2half2(h2, h3);
    ((__half2*)lo)[2 * i]     = __halves2half2(l0, l1);
    ((__half2*)lo)[2 * i + 1] = __halves2half2(l2, l3);
}

// ---------------- pack ALL weights (both layers, 3 types) -> Bcat fp16 ----------------
__global__ void pack_weights_kernel(const float* __restrict__ Wl1, const float* __restrict__ Wr1,
                                    const float* __restrict__ Wl2, const float* __restrict__ Wr2,
                                    __half* __restrict__ th) {
    int idx = blockIdx.x * 256 + threadIdx.x;
    const int L1 = 3 * 128 * 512;
    const int TOT = L1 + 3 * 256 * 512;
    if (idx >= TOT) return;
    float v;
    if (idx < L1) {
        int t = idx / (128 * 512), rem = idx % (128 * 512);
        int k = rem >> 9, c = rem & 511;
        v = (c < 256) ? Wl1[(size_t)t * 128 * 256 + k * 256 + c]
                      : Wr1[(size_t)t * 128 * 256 + k * 256 + (c - 256)];
    } else {
        int j = idx - L1;
        int t = j / (256 * 512), rem = j % (256 * 512);
        int k = rem >> 9, c = rem & 511;
        v = (c < 256) ? Wl2[(size_t)t * 256 * 256 + k * 256 + c]
                      : Wr2[(size_t)t * 256 * 256 + k * 256 + (c - 256)];
    }
    th[idx] = __float2half(v);
}

// ---------------- CSR build (all types, global padded node ids) ----------------
__global__ void hist_kernel(const int* __restrict__ d0, const int* __restrict__ d1,
                            const int* __restrict__ d2, int* __restrict__ deg,
                            int E0, int E1, int E2, int P1, int P2) {
    int e = blockIdx.x * 256 + threadIdx.x;
    int dv;
    if (e < E0) dv = d0[e];
    else if (e < E0 + E1) dv = d1[e - E0] + P1;
    else if (e < E0 + E1 + E2) dv = d2[e - E0 - E1] + P2;
    else return;
    atomicAdd(&deg[dv], 1);
}

__global__ void scan_bsum_kernel(const int* __restrict__ deg, int* __restrict__ bsum, int N) {
    __shared__ int sh[256];
    int b = blockIdx.x, t = threadIdx.x;
    int s = 0;
    for (int j = t; j < 1024; j += 256) {
        int i = b * 1024 + j;
        if (i < N) s += deg[i];
    }
    sh[t] = s;
    __syncthreads();
    for (int off = 128; off > 0; off >>= 1) {
        if (t < off) sh[t] += sh[t + off];
        __syncthreads();
    }
    if (t == 0) bsum[b] = sh[0];
}

__global__ void scan_boff_kernel(int* __restrict__ bsum, int* __restrict__ rowptr,
                                 int nb, int N) {
    if (threadIdx.x == 0) {
        int acc = 0;
        for (int b = 0; b < nb; b++) { int v = bsum[b]; bsum[b] = acc; acc += v; }
        rowptr[N] = acc;
    }
}

__global__ void scan_final_kernel(const int* __restrict__ deg, const int* __restrict__ bsum,
                                  int* __restrict__ rowptr, int N) {
    __shared__ int sh[1024];
    int b = blockIdx.x, t = threadIdx.x;
    int i = b * 1024 + t;
    int v = (i < N) ? deg[i] : 0;
    sh[t] = v;
    __syncthreads();
    for (int off = 1; off < 1024; off <<= 1) {
        int u = (t >= off) ? sh[t - off] : 0;
        __syncthreads();
        sh[t] += u;
        __syncthreads();
    }
    if (i < N) rowptr[i] = bsum[b] + sh[t] - v;
}

__global__ void scatter_kernel(const int* __restrict__ s0, const int* __restrict__ d0,
                               const int* __restrict__ s1, const int* __restrict__ d1,
                               const int* __restrict__ s2, const int* __restrict__ d2,
                               const int* __restrict__ rowptr, int* __restrict__ cursor,
                               int* __restrict__ csrsrc,
                               int E0, int E1, int E2, int P1, int P2) {
    int e = blockIdx.x * 256 + threadIdx.x;
    int sv, dv;
    if (e < E0)                { sv = s0[e];            dv = d0[e]; }
    else if (e < E0 + E1)      { sv = s1[e - E0] + P1;  dv = d1[e - E0] + P1; }
    else if (e < E0 + E1 + E2) { sv = s2[e - E0 - E1] + P2; dv = d2[e - E0 - E1] + P2; }
    else return;
    int pos = atomicAdd(&cursor[dv], 1);
    csrsrc[rowptr[dv] + pos] = sv;
}

// ---------------- GATv2 aggregate (all types): one warp per dst node ----------------
// 2-edge unrolled: interleaved score/shfl chains + joint online-softmax update.
__global__ __launch_bounds__(256) void gat_kernel(
    const float* __restrict__ hl, const float* __restrict__ hr,
    const int* __restrict__ rowptr, const int* __restrict__ csrsrc,
    const float* __restrict__ attAll, const float* __restrict__ biasAll,
    float* __restrict__ out, int P1, int P2, int N0, int N1, int N2, int NPAD)
{
    int d = (blockIdx.x * blockDim.x + threadIdx.x) >> 5;
    if (d >= NPAD) return;
    int t  = (d >= P2) ? 2 : (d >= P1 ? 1 : 0);
    int Pt = (t == 2) ? P2 : (t == 1 ? P1 : 0);
    int Nt = (t == 2) ? N2 : (t == 1 ? N1 : N0);
    if (d - Pt >= Nt) return;                     // pad node
    int lane = threadIdx.x & 31;
    int base = lane * 8;
    const float* att  = attAll + t * 256;
    const float* bias = biasAll + t * 256;

    float4 at0 = *(const float4*)(att + base);
    float4 at1 = *(const float4*)(att + base + 4);
    float atv[8] = {at0.x, at0.y, at0.z, at0.w, at1.x, at1.y, at1.z, at1.w};

    const float* hrp = hr + (size_t)d * 256 + base;
    float4 r0 = *(const float4*)hrp;
    float4 r1 = *(const float4*)(hrp + 4);
    float hrv[8] = {r0.x, r0.y, r0.z, r0.w, r1.x, r1.y, r1.z, r1.w};

    float m = -1.0e30f, den = 0.f;
    float acc[8] = {0.f, 0.f, 0.f, 0.f, 0.f, 0.f, 0.f, 0.f};

    int e0 = rowptr[d], e1 = rowptr[d + 1];
    int e = e0 - 1;                               // e == e0-1 -> self loop

    for (; e + 1 < e1; e += 2) {
        int s0 = (e < e0) ? d : csrsrc[e];
        int s1 = csrsrc[e + 1];
        const float* hp0 = hl + (size_t)s0 * 256 + base;
        const float* hp1 = hl + (size_t)s1 * 256 + base;
        float4 a0 = *(const float4*)hp0;
        float4 a1 = *(const float4*)(hp0 + 4);
        float4 b0 = *(const float4*)hp1;
        float4 b1 = *(const float4*)(hp1 + 4);
        float hva[8] = {a0.x, a0.y, a0.z, a0.w, a1.x, a1.y, a1.z, a1.w};
        float hvb[8] = {b0.x, b0.y, b0.z, b0.w, b1.x, b1.y, b1.z, b1.w};

        float pa = 0.f, pb = 0.f;
#pragma unroll
        for (int j = 0; j < 8; j++) {
            float va = hva[j] + hrv[j];
            float vb = hvb[j] + hrv[j];
            va = (va > 0.f) ? va : 0.2f * va;
            vb = (vb > 0.f) ? vb : 0.2f * vb;
            pa += va * atv[j];
            pb += vb * atv[j];
        }
        pa += __shfl_xor_sync(0xffffffffu, pa, 1);
        pb += __shfl_xor_sync(0xffffffffu, pb, 1);
        pa += __shfl_xor_sync(0xffffffffu, pa, 2);
        pb += __shfl_xor_sync(0xffffffffu, pb, 2);
        pa += __shfl_xor_sync(0xffffffffu, pa, 4);
        pb += __shfl_xor_sync(0xffffffffu, pb, 4);

        float nm = fmaxf(m, fmaxf(pa, pb));
        float f  = __expf(m - nm);
        float wa = __expf(pa - nm);
        float wb = __expf(pb - nm);
        den = den * f + wa + wb;
        m = nm;
#pragma unroll
        for (int j = 0; j < 8; j++)
            acc[j] = acc[j] * f + wa * hva[j] + wb * hvb[j];
    }

    if (e < e1) {                                 // tail (single edge / lone self loop)
        int s = (e < e0) ? d : csrsrc[e];
        const float* hp = hl + (size_t)s * 256 + base;
        float4 h0 = *(const float4*)hp;
        float4 h1 = *(const float4*)(hp + 4);
        float hv[8] = {h0.x, h0.y, h0.z, h0.w, h1.x, h1.y, h1.z, h1.w};
        float p = 0.f;
#pragma unroll
        for (int j = 0; j < 8; j++) {
            float v = hv[j] + hrv[j];
            v = (v > 0.f) ? v : 0.2f * v;
            p += v * atv[j];
        }
        p += __shfl_xor_sync(0xffffffffu, p, 1);
        p += __shfl_xor_sync(0xffffffffu, p, 2);
        p += __shfl_xor_sync(0xffffffffu, p, 4);
        float nm = fmaxf(m, p);
        float f  = __expf(m - nm);
        float wv = __expf(p - nm);
        den = den * f + wv;
        m = nm;
#pragma unroll
        for (int j = 0; j < 8; j++) acc[j] = acc[j] * f + wv * hv[j];
    }

    float inv = 1.f / (den + 1e-16f);
    float* op = out + (size_t)d * 256 + base;
    float4 o0, o1;
    o0.x = acc[0] * inv + bias[base + 0];
    o0.y = acc[1] * inv + bias[base + 1];
    o0.z = acc[2] * inv + bias[base + 2];
    o0.w = acc[3] * inv + bias[base + 3];
    o1.x = acc[4] * inv + bias[base + 4];
    o1.y = acc[5] * inv + bias[base + 5];
    o1.z = acc[6] * inv + bias[base + 6];
    o1.w = acc[7] * inv + bias[base + 7];
    *(float4*)op       = o0;
    *(float4*)(op + 4) = o1;
}

// ---------------- BatchNorm (per-type stats, grid.y = type) ----------------
__global__ void bn_stats_kernel(const float* __restrict__ x,
                                float* __restrict__ bnsum, float* __restrict__ bnsq,
                                int P1, int P2, int N0, int N1, int N2) {
    int t = blockIdx.y;
    int Pt = (t == 2) ? P2 : (t == 1 ? P1 : 0);
    int Nt = (t == 2) ? N2 : (t == 1 ? N1 : N0);
    int c = threadIdx.x;
    float s = 0.f, q = 0.f;
    for (int r = blockIdx.x; r < Nt; r += gridDim.x) {
        float v = x[(size_t)(Pt + r) * 256 + c];
        s += v;
        q += v * v;
    }
    atomicAdd(&bnsum[t * 256 + c], s);
    atomicAdd(&bnsq[t * 256 + c], q);
}

__global__ void bn_final_kernel(const float* __restrict__ bnsum, const float* __restrict__ bnsq,
                                const float* __restrict__ g, const float* __restrict__ b,
                                float* __restrict__ scale, float* __restrict__ shift,
                                int N0, int N1, int N2) {
    int c = threadIdx.x + blockIdx.x * 256;      // 0..767
    int t = c >> 8;
    int Nt = (t == 2) ? N2 : (t == 1 ? N1 : N0);
    float invn = 1.f / (float)Nt;
    float mean = bnsum[c] * invn;
    float var  = bnsq[c] * invn - mean * mean;
    float sc   = g[c] * rsqrtf(var + 1e-5f);
    scale[c] = sc;
    shift[c] = b[c] - mean * sc;
}

// bn + leaky-relu over all padded rows; optional fp16 hi/lo emit for next GEMM
__global__ void bn_apply_kernel(const float* __restrict__ in, float* __restrict__ outp,
                                __half* __restrict__ oh, __half* __restrict__ ol,
                                const float* __restrict__ scale, const float* __restrict__ shift,
                                int P1, int P2, int NPAD, int do_split) {
    int i = blockIdx.x * 256 + threadIdx.x;      // float4 over NPAD*256
    if (i >= NPAD * 64) return;
    int row = i >> 6;
    int t = (row >= P2) ? 2 : (row >= P1 ? 1 : 0);
    int c = t * 256 + (i & 63) * 4;
    float4 v  = *(const float4*)(in + (size_t)i * 4);
    float4 sc = *(const float4*)(scale + c);
    float4 sh = *(const float4*)(shift + c);
    float a0 = v.x * sc.x + sh.x;
    float a1 = v.y * sc.y + sh.y;
    float a2 = v.z * sc.z + sh.z;
    float a3 = v.w * sc.w + sh.w;
    float4 o;
    o.x = (a0 > 0.f) ? a0 : 0.01f * a0;
    o.y = (a1 > 0.f) ? a1 : 0.01f * a1;
    o.z = (a2 > 0.f) ? a2 : 0.01f * a2;
    o.w = (a3 > 0.f) ? a3 : 0.01f * a3;
    *(float4*)(outp + (size_t)i * 4) = o;
    if (do_split) {
        __half h0 = __float2half(o.x), h1 = __float2half(o.y);
        __half h2 = __float2half(o.z), h3 = __float2half(o.w);
        __half l0 = __float2half(o.x - __half2float(h0));
        __half l1 = __float2half(o.y - __half2float(h1));
        __half l2 = __float2half(o.z - __half2float(h2));
        __half l3 = __float2half(o.w - __half2float(h3));
        ((__half2*)oh)[2 * i]     = __halves2half2(h0, h1);
        ((__half2*)oh)[2 * i + 1] = __halves2half2(h2, h3);
        ((__half2*)ol)[2 * i]     = __halves2half2(l0, l1);
        ((__half2*)ol)[2 * i + 1] = __halves2half2(l2, l3);
    }
}

// ---------------- Classifier: warp per (compact) output row ----------------
__global__ __launch_bounds__(256) void classifier_kernel(
    const float* __restrict__ h, const float* __restrict__ cW,
    const float* __restrict__ cb, float* __restrict__ outp,
    int P1, int P2, int N0, int N1, int N2)
{
    int idx = (blockIdx.x * blockDim.x + threadIdx.x) >> 5;    // compact row
    int NT = N0 + N1 + N2;
    if (idx >= NT) return;
    int t  = (idx >= N0 + N1) ? 2 : (idx >= N0 ? 1 : 0);
    int Ct = (t == 2) ? N0 + N1 : (t == 1 ? N0 : 0);
    int Pt = (t == 2) ? P2 : (t == 1 ? P1 : 0);
    int row = Pt + (idx - Ct);
    int lane = threadIdx.x & 31;

    const float* hp = h + (size_t)row * 256 + lane * 8;
    float4 h0 = *(const float4*)hp;
    float4 h1 = *(const float4*)(hp + 4);
    float hv[8] = {h0.x, h0.y, h0.z, h0.w, h1.x, h1.y, h1.z, h1.w};

    const float* wp = cW + lane * 16;
    float4 w0 = *(const float4*)(wp + 0);
    float4 w1 = *(const float4*)(wp + 4);
    float4 w2 = *(const float4*)(wp + 8);
    float4 w3 = *(const float4*)(wp + 12);
    float wv[16] = {w0.x, w0.y, w0.z, w0.w, w1.x, w1.y, w1.z, w1.w,
                    w2.x, w2.y, w2.z, w2.w, w3.x, w3.y, w3.z, w3.w};

    float c0 = 0.f, c1 = 0.f;
#pragma unroll
    for (int j = 0; j < 8; j++) {
        c0 += hv[j] * wv[2 * j];
        c1 += hv[j] * wv[2 * j + 1];
    }
#pragma unroll
    for (int off = 16; off > 0; off >>= 1) {
        c0 += __shfl_xor_sync(0xffffffffu, c0, off);
        c1 += __shfl_xor_sync(0xffffffffu, c1, off);
    }
    if (lane == 0) {
        outp[(size_t)idx * 2 + 0] = c0 + cb[0];
        outp[(size_t)idx * 2 + 1] = c1 + cb[1];
    }
}

// ---------------- launch ----------------
extern "C" void kernel_launch(void* const* d_in, const int* in_sizes, int n_in,
                              void* d_out, int out_size) {
    const float* x[3];
    const int*   ei[3];
    for (int i = 0; i < 3; i++) {
        x[i]  = (const float*)d_in[i];
        ei[i] = (const int*)d_in[3 + i];
    }
    const float* Wl1  = (const float*)d_in[6];
    const float* Wr1  = (const float*)d_in[7];
    const float* att1 = (const float*)d_in[8];
    const float* b1   = (const float*)d_in[9];
    const float* Wl2  = (const float*)d_in[10];
    const float* Wr2  = (const float*)d_in[11];
    const float* att2 = (const float*)d_in[12];
    const float* b2   = (const float*)d_in[13];
    const float* bng  = (const float*)d_in[14];
    const float* bnb  = (const float*)d_in[15];
    const float* cW   = (const float*)d_in[16];
    const float* cb   = (const float*)d_in[17];
    float* out = (float*)d_out;

    float *hl, *hr, *h, *hn, *bnsum, *bnsq, *scale, *shift;
    __half *Ah, *Al, *Bh;
    int *rowptr, *csrsrc, *deg, *cursor, *bsum;
    cudaGetSymbolAddress((void**)&hl,     g_hl);
    cudaGetSymbolAddress((void**)&hr,     g_hr);
    cudaGetSymbolAddress((void**)&h,      g_h);
    cudaGetSymbolAddress((void**)&hn,     g_hn);
    cudaGetSymbolAddress((void**)&Ah,     g_Ah);
    cudaGetSymbolAddress((void**)&Al,     g_Al);
    cudaGetSymbolAddress((void**)&Bh,     g_Bh);
    cudaGetSymbolAddress((void**)&rowptr, g_rowptr);
    cudaGetSymbolAddress((void**)&csrsrc, g_csrsrc);
    cudaGetSymbolAddress((void**)&deg,    g_deg);
    cudaGetSymbolAddress((void**)&cursor, g_cursor);
    cudaGetSymbolAddress((void**)&bsum,   g_bsum);
    cudaGetSymbolAddress((void**)&bnsum,  g_bnsum);
    cudaGetSymbolAddress((void**)&bnsq,   g_bnsq);
    cudaGetSymbolAddress((void**)&scale,  g_scale);
    cudaGetSymbolAddress((void**)&shift,  g_shift);

    cudaFuncSetAttribute(gemm_mma_kernel,
                         cudaFuncAttributeMaxDynamicSharedMemorySize, GEMM_SMEM);

    // geometry
    int N0 = in_sizes[0] / 128, N1 = in_sizes[1] / 128, N2 = in_sizes[2] / 128;
    int E0 = in_sizes[3] / 2,   E1 = in_sizes[4] / 2,   E2 = in_sizes[5] / 2;
    int T0 = (N0 + 127) / 128, T1 = (N1 + 127) / 128, T2 = (N2 + 127) / 128;
    int P1 = T0 * 128, P2 = P1 + T1 * 128;
    int NPAD = P2 + T2 * 128;
    int ET = E0 + E1 + E2;
    int ntile = NPAD / 128;
    int nb = (NPAD + 1023) / 1024;

    // --- prep; layer-1 GEMM at launch index 4 so ncu (-s 5 -c 1 slot) profiles it ---
    split_x_kernel<<<(NPAD * 32 + 255) / 256, 256>>>(x[0], x[1], x[2], Ah, Al,
                                                     P1, P2, N0, N1, N2, NPAD);   // 0
    {
        int tot = 3 * 128 * 512 + 3 * 256 * 512;
        pack_weights_kernel<<<(tot + 255) / 256, 256>>>(Wl1, Wr1, Wl2, Wr2, Bh);  // 1
    }
    cudaMemsetAsync(deg, 0, NPAD * sizeof(int), 0);                               // 2
    hist_kernel<<<(ET + 255) / 256, 256>>>(ei[0] + E0, ei[1] + E1, ei[2] + E2,
                                           deg, E0, E1, E2, P1, P2);              // 3

    dim3 gg(4, ntile);
    gemm_mma_kernel<<<gg, 256, GEMM_SMEM>>>(Ah, Al, Bh, hl, hr,
                                            P1, P2, N0, N1, N2, 128, 0);          // 4 (profiled)

    scan_bsum_kernel<<<nb, 256>>>(deg, bsum, NPAD);
    scan_boff_kernel<<<1, 32>>>(bsum, rowptr, nb, NPAD);
    scan_final_kernel<<<nb, 1024>>>(deg, bsum, rowptr, NPAD);
    cudaMemsetAsync(cursor, 0, NPAD * sizeof(int), 0);
    scatter_kernel<<<(ET + 255) / 256, 256>>>(ei[0], ei[0] + E0, ei[1], ei[1] + E1,
                                              ei[2], ei[2] + E2,
                                              rowptr, cursor, csrsrc, E0, E1, E2, P1, P2);

    for (int layer = 0; layer < 2; layer++) {
        if (layer == 1) {
            gemm_mma_kernel<<<gg, 256, GEMM_SMEM>>>(Ah, Al, Bh, hl, hr,
                                                    P1, P2, N0, N1, N2, 256, L2_WOFF);
        }
        const float* at = (layer == 0) ? att1 : att2;
        const float* bs = (layer == 0) ? b1 : b2;

        gat_kernel<<<(NPAD * 32 + 255) / 256, 256>>>(hl, hr, rowptr, csrsrc, at, bs, h,
                                                     P1, P2, N0, N1, N2, NPAD);

        cudaMemsetAsync(bnsum, 0, 768 * sizeof(float), 0);
        cudaMemsetAsync(bnsq,  0, 768 * sizeof(float), 0);
        {
            dim3 gs(128, 3);
            bn_stats_kernel<<<gs, 256>>>(h, bnsum, bnsq, P1, P2, N0, N1, N2);
        }
        bn_final_kernel<<<3, 256>>>(bnsum, bnsq, bng, bnb, scale, shift, N0, N1, N2);
        bn_apply_kernel<<<(NPAD * 64 + 255) / 256, 256>>>(
            h, hn, Ah, Al, scale, shift, P1, P2, NPAD, layer == 0 ? 1 : 0);
    }

    classifier_kernel<<<((N0 + N1 + N2) * 32 + 255) / 256, 256>>>(
        hn, cW, cb, out, P1, P2, N0, N1, N2);
}